// round 4
// baseline (speedup 1.0000x reference)
#include <cuda_runtime.h>
#include <cuda_bf16.h>
#include <math.h>

#define D_MODEL 512
#define T_LEN   2048
#define BATCH   4
#define NROWS   (BATCH * T_LEN)   // 8192
#define N_HEADS 8
#define D_K     64

typedef unsigned int uint;

// -------- scratch (no allocs allowed) --------
__device__ float          g_h [NROWS * D_MODEL];   // LN1(x)+PE fp32 (residual1)
__device__ __nv_bfloat16  g_hh[NROWS * D_MODEL];   // hi split of h
__device__ __nv_bfloat16  g_hl[NROWS * D_MODEL];   // lo split of h
__device__ float          g_q [NROWS * D_MODEL];   // [B,H,T,64]
__device__ float          g_k [NROWS * D_MODEL];
__device__ float          g_v [NROWS * D_MODEL];
__device__ __nv_bfloat16  g_oh[NROWS * D_MODEL];   // attention out, [B,T,512], hi
__device__ __nv_bfloat16  g_ol[NROWS * D_MODEL];   // lo
__device__ float          g_y [NROWS * D_MODEL];   // o @ wfc fp32
__device__ __nv_bfloat16  g_wh[4 * D_MODEL * D_MODEL];
__device__ __nv_bfloat16  g_wl[4 * D_MODEL * D_MODEL];

__device__ __forceinline__ void bf16_split(float x, __nv_bfloat16& h, __nv_bfloat16& l) {
    h = __float2bfloat16(x);
    l = __float2bfloat16(x - __bfloat162float(h));
}

// ============================================================
// Weight split: fp32 -> (hi, lo) bf16
// ============================================================
__global__ __launch_bounds__(256) void split_w_kernel(
    const float* __restrict__ w, __nv_bfloat16* __restrict__ wh,
    __nv_bfloat16* __restrict__ wl)
{
    int i = blockIdx.x * 256 + threadIdx.x;   // grid covers 512*512
    float x = w[i];
    __nv_bfloat16 h, l;
    bf16_split(x, h, l);
    wh[i] = h; wl[i] = l;
}

// ============================================================
// Kernel 1: LayerNorm(eps=1e-5) + sinusoidal PE, emits fp32 + bf16 split
// ============================================================
__global__ __launch_bounds__(128) void ln1_pe_kernel(
    const float* __restrict__ x,
    const float* __restrict__ gam,
    const float* __restrict__ bet,
    float* __restrict__ h_out,
    __nv_bfloat16* __restrict__ hh_out,
    __nv_bfloat16* __restrict__ hl_out)
{
    int r   = blockIdx.x;
    int tid = threadIdx.x;
    const float4 xv = ((const float4*)(x + (size_t)r * D_MODEL))[tid];

    float sum = xv.x + xv.y + xv.z + xv.w;
    float sq  = xv.x*xv.x + xv.y*xv.y + xv.z*xv.z + xv.w*xv.w;
    #pragma unroll
    for (int off = 16; off; off >>= 1) {
        sum += __shfl_xor_sync(0xffffffffu, sum, off);
        sq  += __shfl_xor_sync(0xffffffffu, sq,  off);
    }
    __shared__ float s1[4], s2[4];
    if ((tid & 31) == 0) { s1[tid >> 5] = sum; s2[tid >> 5] = sq; }
    __syncthreads();
    sum = s1[0] + s1[1] + s1[2] + s1[3];
    sq  = s2[0] + s2[1] + s2[2] + s2[3];

    float mean = sum * (1.0f / D_MODEL);
    float var  = sq  * (1.0f / D_MODEL) - mean * mean;
    float rstd = rsqrtf(var + 1e-5f);

    int t  = r & (T_LEN - 1);
    int c0 = tid * 4;
    const float* xp = (const float*)&xv;
    float4 hv; float* hp = (float*)&hv;
    __nv_bfloat16 hb[4], lb[4];
    #pragma unroll
    for (int u = 0; u < 4; u++) {
        int c = c0 + u;
        float div = expf((float)(c & ~1) * (-9.2103403719761836f / 512.0f));
        float ang = (float)t * div;
        float pe  = (c & 1) ? cosf(ang) : sinf(ang);
        hp[u] = (xp[u] - mean) * rstd * gam[c] + bet[c] + pe;
        bf16_split(hp[u], hb[u], lb[u]);
    }
    ((float4*)(h_out + (size_t)r * D_MODEL))[tid] = hv;
    size_t base = (size_t)r * D_MODEL + c0;
    *(__nv_bfloat162*)(hh_out + base    ) = __nv_bfloat162(hb[0], hb[1]);
    *(__nv_bfloat162*)(hh_out + base + 2) = __nv_bfloat162(hb[2], hb[3]);
    *(__nv_bfloat162*)(hl_out + base    ) = __nv_bfloat162(lb[0], lb[1]);
    *(__nv_bfloat162*)(hl_out + base + 2) = __nv_bfloat162(lb[2], lb[3]);
}

// ============================================================
// Kernel 2: bf16 tensor-core GEMM with 2-term compensation
// C[8192,512] = (Ah+Al)[8192,512] @ (Wh+Wl)[512,512]  (3 mma passes)
// BM=128 BN=64 BK=32, 256 threads (8 warps, 4x2), warp tile 32x32.
// MODE 0: row-major out.  MODE 1: scatter to [B,H,T,64].
// ============================================================
__device__ __forceinline__ void mma_bf16(float* d, const uint* a, const uint* b) {
    asm volatile(
        "mma.sync.aligned.m16n8k16.row.col.f32.bf16.bf16.f32 "
        "{%0,%1,%2,%3},{%4,%5,%6,%7},{%8,%9},{%0,%1,%2,%3};\n"
        : "+f"(d[0]), "+f"(d[1]), "+f"(d[2]), "+f"(d[3])
        : "r"(a[0]), "r"(a[1]), "r"(a[2]), "r"(a[3]), "r"(b[0]), "r"(b[1]));
}

template<int MODE>
__global__ __launch_bounds__(256) void gemm_bf16(
    const __nv_bfloat16* __restrict__ Ah, const __nv_bfloat16* __restrict__ Al,
    const __nv_bfloat16* __restrict__ Wh, const __nv_bfloat16* __restrict__ Wl,
    float* __restrict__ C)
{
    const int K = 512, N = 512;
    __shared__ __nv_bfloat16 sAh[128][40], sAl[128][40];   // [m][k], pad 8
    __shared__ __nv_bfloat16 sWh[64][40],  sWl[64][40];    // [n][k] (transposed)

    int tid  = threadIdx.x;
    int m0   = blockIdx.y * 128;
    int n0   = blockIdx.x * 64;
    int warp = tid >> 5, lane = tid & 31;
    int wm   = (warp >> 1) * 32;        // warp m offset (0,32,64,96)
    int wn   = (warp & 1) * 32;         // warp n offset (0,32)
    int g    = lane >> 2, t = lane & 3;

    float acc[2][4][4];
    #pragma unroll
    for (int i = 0; i < 2; i++)
        #pragma unroll
        for (int j = 0; j < 4; j++)
            #pragma unroll
            for (int e = 0; e < 4; e++) acc[i][j][e] = 0.0f;

    for (int k0 = 0; k0 < K; k0 += 32) {
        __syncthreads();
        // A tiles: 128x32 bf16 = 2048 uints each
        #pragma unroll
        for (int i = 0; i < 8; i++) {
            int idx = tid + i * 256;
            int r = idx >> 4, c = (idx & 15) * 2;
            *(uint*)&sAh[r][c] = *(const uint*)(Ah + (size_t)(m0 + r) * K + k0 + c);
            *(uint*)&sAl[r][c] = *(const uint*)(Al + (size_t)(m0 + r) * K + k0 + c);
        }
        // W tiles: 32(k) x 64(n), transpose into [n][k]
        #pragma unroll
        for (int i = 0; i < 4; i++) {
            int idx = tid + i * 256;
            int kk = idx >> 5, nn = (idx & 31) * 2;
            __nv_bfloat162 h2 = *(const __nv_bfloat162*)(Wh + (size_t)(k0 + kk) * N + n0 + nn);
            __nv_bfloat162 l2 = *(const __nv_bfloat162*)(Wl + (size_t)(k0 + kk) * N + n0 + nn);
            sWh[nn][kk] = h2.x; sWh[nn + 1][kk] = h2.y;
            sWl[nn][kk] = l2.x; sWl[nn + 1][kk] = l2.y;
        }
        __syncthreads();

        #pragma unroll
        for (int ks = 0; ks < 32; ks += 16) {
            uint ah[2][4], al[2][4], bh[4][2], bl[4][2];
            #pragma unroll
            for (int mt = 0; mt < 2; mt++) {
                int mr = wm + mt * 16;
                ah[mt][0] = *(uint*)&sAh[mr + g    ][ks + t*2    ];
                ah[mt][1] = *(uint*)&sAh[mr + g + 8][ks + t*2    ];
                ah[mt][2] = *(uint*)&sAh[mr + g    ][ks + t*2 + 8];
                ah[mt][3] = *(uint*)&sAh[mr + g + 8][ks + t*2 + 8];
                al[mt][0] = *(uint*)&sAl[mr + g    ][ks + t*2    ];
                al[mt][1] = *(uint*)&sAl[mr + g + 8][ks + t*2    ];
                al[mt][2] = *(uint*)&sAl[mr + g    ][ks + t*2 + 8];
                al[mt][3] = *(uint*)&sAl[mr + g + 8][ks + t*2 + 8];
            }
            #pragma unroll
            for (int nt = 0; nt < 4; nt++) {
                int nr = wn + nt * 8 + g;
                bh[nt][0] = *(uint*)&sWh[nr][ks + t*2    ];
                bh[nt][1] = *(uint*)&sWh[nr][ks + t*2 + 8];
                bl[nt][0] = *(uint*)&sWl[nr][ks + t*2    ];
                bl[nt][1] = *(uint*)&sWl[nr][ks + t*2 + 8];
            }
            #pragma unroll
            for (int mt = 0; mt < 2; mt++)
                #pragma unroll
                for (int nt = 0; nt < 4; nt++) {
                    mma_bf16(acc[mt][nt], ah[mt], bh[nt]);
                    mma_bf16(acc[mt][nt], ah[mt], bl[nt]);
                    mma_bf16(acc[mt][nt], al[mt], bh[nt]);
                }
        }
    }

    // epilogue
    #pragma unroll
    for (int mt = 0; mt < 2; mt++)
        #pragma unroll
        for (int nt = 0; nt < 4; nt++) {
            float* a = acc[mt][nt];
            int m = m0 + wm + mt * 16 + g;
            int n = n0 + wn + nt * 8 + t * 2;
            if (MODE == 0) {
                *(float2*)(C + (size_t)m * N + n)       = make_float2(a[0], a[1]);
                *(float2*)(C + (size_t)(m + 8) * N + n) = make_float2(a[2], a[3]);
            } else {
                #pragma unroll
                for (int e = 0; e < 4; e++) {
                    int mm = m + (e >> 1) * 8;
                    int nn = n + (e & 1);
                    int bb = mm >> 11, tt = mm & (T_LEN - 1);
                    int hh = nn >> 6,  dd = nn & 63;
                    C[(((size_t)bb * N_HEADS + hh) * T_LEN + tt) * D_K + dd] = a[e];
                }
            }
        }
}

// ============================================================
// Kernel 3: causal flash attention (fp32), load-balanced.
// Block = two independent 64-thread groups handling half-tiles p and 31-p
// (constant work per block). Named barriers per group, disjoint smem.
// Emits output already bf16-split for the wfc GEMM.
// ============================================================
__global__ __launch_bounds__(128) void attn_kernel(
    const float* __restrict__ q,
    const float* __restrict__ k,
    const float* __restrict__ v,
    __nv_bfloat16* __restrict__ oh_out,
    __nv_bfloat16* __restrict__ ol_out)
{
    int p   = blockIdx.x;            // 0..15
    int bh  = blockIdx.y;            // 0..31
    int b   = bh >> 3;
    int h   = bh & 7;
    int g   = threadIdx.x >> 6;      // group 0/1
    int rt  = threadIdx.x & 63;
    int ht  = (g == 0) ? p : (31 - p);   // half-tile index 0..31
    int qi  = ht * 64 + rt;
    int barid = g + 1;

    __shared__ float sK[2][32][64];
    __shared__ float sV[2][32][64];

    float qreg[64];
    {
        const float4* q4 = (const float4*)(q + ((size_t)bh * T_LEN + qi) * D_K);
        #pragma unroll
        for (int i = 0; i < 16; i++) {
            float4 tv = q4[i];
            qreg[i*4+0] = tv.x * 0.125f;
            qreg[i*4+1] = tv.y * 0.125f;
            qreg[i*4+2] = tv.z * 0.125f;
            qreg[i*4+3] = tv.w * 0.125f;
        }
    }

    float m = -1e30f, l = 0.0f;
    float o[64];
    #pragma unroll
    for (int d = 0; d < 64; d++) o[d] = 0.0f;

    int ntiles = 2 * (ht + 1);
    for (int tile = 0; tile < ntiles; tile++) {
        int k0 = tile * 32;
        asm volatile("bar.sync %0, 64;" :: "r"(barid));
        {
            const float4* K4 = (const float4*)(k + ((size_t)bh * T_LEN + k0) * D_K);
            const float4* V4 = (const float4*)(v + ((size_t)bh * T_LEN + k0) * D_K);
            float4* sK4 = (float4*)&sK[g][0][0];
            float4* sV4 = (float4*)&sV[g][0][0];
            #pragma unroll
            for (int i = 0; i < 8; i++) {
                sK4[rt + i * 64] = K4[rt + i * 64];
                sV4[rt + i * 64] = V4[rt + i * 64];
            }
        }
        asm volatile("bar.sync %0, 64;" :: "r"(barid));

        float s[32];
        #pragma unroll
        for (int j = 0; j < 32; j++) {
            float acc = 0.0f;
            #pragma unroll
            for (int d = 0; d < 64; d++) acc += qreg[d] * sK[g][j][d];
            s[j] = (k0 + j <= qi) ? acc : -1e30f;
        }

        float tm = m;
        #pragma unroll
        for (int j = 0; j < 32; j++) tm = fmaxf(tm, s[j]);

        float factor = __expf(m - tm);
        l *= factor;
        #pragma unroll
        for (int d = 0; d < 64; d++) o[d] *= factor;

        #pragma unroll
        for (int j = 0; j < 32; j++) {
            float pj = __expf(s[j] - tm);
            l += pj;
            #pragma unroll
            for (int d = 0; d < 64; d++) o[d] += pj * sV[g][j][d];
        }
        m = tm;
    }

    float inv = 1.0f / l;
    size_t base = ((size_t)b * T_LEN + qi) * D_MODEL + h * D_K;
    #pragma unroll
    for (int i = 0; i < 32; i++) {
        float v0 = o[i*2+0] * inv;
        float v1 = o[i*2+1] * inv;
        __nv_bfloat16 h0, l0, h1, l1;
        bf16_split(v0, h0, l0);
        bf16_split(v1, h1, l1);
        *(__nv_bfloat162*)(oh_out + base + i*2) = __nv_bfloat162(h0, h1);
        *(__nv_bfloat162*)(ol_out + base + i*2) = __nv_bfloat162(l0, l1);
    }
}

// ============================================================
// Kernel 4: residual + LayerNorm(eps=1e-6) + outer residual
// ============================================================
__global__ __launch_bounds__(128) void ln2_kernel(
    const float* __restrict__ y,
    const float* __restrict__ h,
    const float* __restrict__ x,
    const float* __restrict__ g2,
    const float* __restrict__ b2,
    float* __restrict__ out)
{
    int r   = blockIdx.x;
    int tid = threadIdx.x;
    float4 yv = ((const float4*)(y + (size_t)r * D_MODEL))[tid];
    float4 hv = ((const float4*)(h + (size_t)r * D_MODEL))[tid];
    float4 tv;
    tv.x = yv.x + hv.x; tv.y = yv.y + hv.y;
    tv.z = yv.z + hv.z; tv.w = yv.w + hv.w;

    float sum = tv.x + tv.y + tv.z + tv.w;
    float sq  = tv.x*tv.x + tv.y*tv.y + tv.z*tv.z + tv.w*tv.w;
    #pragma unroll
    for (int off = 16; off; off >>= 1) {
        sum += __shfl_xor_sync(0xffffffffu, sum, off);
        sq  += __shfl_xor_sync(0xffffffffu, sq,  off);
    }
    __shared__ float s1[4], s2[4];
    if ((tid & 31) == 0) { s1[tid >> 5] = sum; s2[tid >> 5] = sq; }
    __syncthreads();
    sum = s1[0] + s1[1] + s1[2] + s1[3];
    sq  = s2[0] + s2[1] + s2[2] + s2[3];

    float mean = sum * (1.0f / D_MODEL);
    float var  = sq  * (1.0f / D_MODEL) - mean * mean;
    float rstd = rsqrtf(var + 1e-6f);

    float4 xv = ((const float4*)(x + (size_t)r * D_MODEL))[tid];
    const float* tp = (const float*)&tv;
    const float* xp = (const float*)&xv;
    int c0 = tid * 4;
    float4 ov; float* op = (float*)&ov;
    #pragma unroll
    for (int u = 0; u < 4; u++) {
        int c = c0 + u;
        op[u] = (tp[u] - mean) * rstd * g2[c] + b2[c] + xp[u];
    }
    ((float4*)(out + (size_t)r * D_MODEL))[tid] = ov;
}

// ============================================================
// launch
// ============================================================
extern "C" void kernel_launch(void* const* d_in, const int* in_sizes, int n_in,
                              void* d_out, int out_size)
{
    const float* x   = (const float*)d_in[0];
    const float* g1  = (const float*)d_in[1];
    const float* b1  = (const float*)d_in[2];
    const float* wq  = (const float*)d_in[3];
    const float* wk  = (const float*)d_in[4];
    const float* wv  = (const float*)d_in[5];
    const float* wfc = (const float*)d_in[6];
    const float* g2  = (const float*)d_in[7];
    const float* b2  = (const float*)d_in[8];
    float* out = (float*)d_out;

    float *ph, *pq, *pk, *pv, *py;
    __nv_bfloat16 *phh, *phl, *poh, *pol, *pwh, *pwl;
    cudaGetSymbolAddress((void**)&ph,  g_h);
    cudaGetSymbolAddress((void**)&phh, g_hh);
    cudaGetSymbolAddress((void**)&phl, g_hl);
    cudaGetSymbolAddress((void**)&pq,  g_q);
    cudaGetSymbolAddress((void**)&pk,  g_k);
    cudaGetSymbolAddress((void**)&pv,  g_v);
    cudaGetSymbolAddress((void**)&poh, g_oh);
    cudaGetSymbolAddress((void**)&pol, g_ol);
    cudaGetSymbolAddress((void**)&py,  g_y);
    cudaGetSymbolAddress((void**)&pwh, g_wh);
    cudaGetSymbolAddress((void**)&pwl, g_wl);

    const int WSZ = D_MODEL * D_MODEL;          // 262144
    split_w_kernel<<<WSZ / 256, 256>>>(wq,  pwh + 0 * WSZ, pwl + 0 * WSZ);
    split_w_kernel<<<WSZ / 256, 256>>>(wk,  pwh + 1 * WSZ, pwl + 1 * WSZ);
    split_w_kernel<<<WSZ / 256, 256>>>(wv,  pwh + 2 * WSZ, pwl + 2 * WSZ);
    split_w_kernel<<<WSZ / 256, 256>>>(wfc, pwh + 3 * WSZ, pwl + 3 * WSZ);

    ln1_pe_kernel<<<NROWS, 128>>>(x, g1, b1, ph, phh, phl);

    dim3 gg(D_MODEL / 64, NROWS / 128);   // (8, 64)
    gemm_bf16<1><<<gg, 256>>>(phh, phl, pwh + 0 * WSZ, pwl + 0 * WSZ, pq);
    gemm_bf16<1><<<gg, 256>>>(phh, phl, pwh + 1 * WSZ, pwl + 1 * WSZ, pk);
    gemm_bf16<1><<<gg, 256>>>(phh, phl, pwh + 2 * WSZ, pwl + 2 * WSZ, pv);

    attn_kernel<<<dim3(16, BATCH * N_HEADS), 128>>>(pq, pk, pv, poh, pol);

    gemm_bf16<0><<<gg, 256>>>(poh, pol, pwh + 3 * WSZ, pwl + 3 * WSZ, py);

    ln2_kernel<<<NROWS, 128>>>(py, ph, x, g2, b2, out);
}

// round 9
// speedup vs baseline: 2.4083x; 2.4083x over previous
#include <cuda_runtime.h>
#include <cuda_bf16.h>
#include <math.h>

#define D_MODEL 512
#define T_LEN   2048
#define BATCH   4
#define NROWS   (BATCH * T_LEN)   // 8192
#define N_HEADS 8
#define D_K     64

typedef unsigned int uint;

// -------- scratch --------
__device__ float          g_h  [NROWS * D_MODEL];  // LN1(x)+PE fp32 (residual1)
__device__ __nv_bfloat16  g_hh [NROWS * D_MODEL];
__device__ __nv_bfloat16  g_hl [NROWS * D_MODEL];
__device__ __nv_bfloat16  g_qh [NROWS * D_MODEL];  // [B,H,T,64]  (pre-scaled by 0.125)
__device__ __nv_bfloat16  g_ql [NROWS * D_MODEL];
__device__ __nv_bfloat16  g_kh [NROWS * D_MODEL];  // [B,H,T,64]
__device__ __nv_bfloat16  g_kl [NROWS * D_MODEL];
__device__ __nv_bfloat16  g_vh [NROWS * D_MODEL];  // [B,H,64,T]  (transposed)
__device__ __nv_bfloat16  g_vl [NROWS * D_MODEL];
__device__ __nv_bfloat16  g_oh [NROWS * D_MODEL];  // attn out [B,T,512]
__device__ __nv_bfloat16  g_ol [NROWS * D_MODEL];
__device__ float          g_y  [NROWS * D_MODEL];
__device__ __nv_bfloat16  g_wh [4 * D_MODEL * D_MODEL];
__device__ __nv_bfloat16  g_wl [4 * D_MODEL * D_MODEL];

__device__ __forceinline__ void bf16_split(float x, __nv_bfloat16& h, __nv_bfloat16& l) {
    h = __float2bfloat16(x);
    l = __float2bfloat16(x - __bfloat162float(h));
}
__device__ __forceinline__ uint packbf(float lo, float hi) {
    uint r;
    asm("cvt.rn.bf16x2.f32 %0, %1, %2;" : "=r"(r) : "f"(hi), "f"(lo));
    return r;
}
__device__ __forceinline__ float lo16f(uint u) { return __uint_as_float(u << 16); }
__device__ __forceinline__ float hi16f(uint u) { return __uint_as_float(u & 0xffff0000u); }

__device__ __forceinline__ void mma_bf16(float* d, const uint* a, const uint* b) {
    asm volatile(
        "mma.sync.aligned.m16n8k16.row.col.f32.bf16.bf16.f32 "
        "{%0,%1,%2,%3},{%4,%5,%6,%7},{%8,%9},{%0,%1,%2,%3};\n"
        : "+f"(d[0]), "+f"(d[1]), "+f"(d[2]), "+f"(d[3])
        : "r"(a[0]), "r"(a[1]), "r"(a[2]), "r"(a[3]), "r"(b[0]), "r"(b[1]));
}

// ============================================================
// Weight split: 4 matrices in one launch
// ============================================================
__global__ __launch_bounds__(256) void split_w_kernel(
    const float* __restrict__ w0, const float* __restrict__ w1,
    const float* __restrict__ w2, const float* __restrict__ w3,
    __nv_bfloat16* __restrict__ wh, __nv_bfloat16* __restrict__ wl)
{
    const int WSZ = D_MODEL * D_MODEL;
    int wsel = blockIdx.y;
    const float* w = (wsel == 0) ? w0 : (wsel == 1) ? w1 : (wsel == 2) ? w2 : w3;
    int i = blockIdx.x * 256 + threadIdx.x;
    float x = w[i];
    __nv_bfloat16 h, l;
    bf16_split(x, h, l);
    wh[wsel * WSZ + i] = h;
    wl[wsel * WSZ + i] = l;
}

// ============================================================
// Kernel 1: LN(eps 1e-5) + sinusoidal PE -> fp32 + bf16 split
// ============================================================
__global__ __launch_bounds__(128) void ln1_pe_kernel(
    const float* __restrict__ x,
    const float* __restrict__ gam,
    const float* __restrict__ bet,
    float* __restrict__ h_out,
    __nv_bfloat16* __restrict__ hh_out,
    __nv_bfloat16* __restrict__ hl_out)
{
    int r   = blockIdx.x;
    int tid = threadIdx.x;
    const float4 xv = ((const float4*)(x + (size_t)r * D_MODEL))[tid];

    float sum = xv.x + xv.y + xv.z + xv.w;
    float sq  = xv.x*xv.x + xv.y*xv.y + xv.z*xv.z + xv.w*xv.w;
    #pragma unroll
    for (int off = 16; off; off >>= 1) {
        sum += __shfl_xor_sync(0xffffffffu, sum, off);
        sq  += __shfl_xor_sync(0xffffffffu, sq,  off);
    }
    __shared__ float s1[4], s2[4];
    if ((tid & 31) == 0) { s1[tid >> 5] = sum; s2[tid >> 5] = sq; }
    __syncthreads();
    sum = s1[0] + s1[1] + s1[2] + s1[3];
    sq  = s2[0] + s2[1] + s2[2] + s2[3];

    float mean = sum * (1.0f / D_MODEL);
    float var  = sq  * (1.0f / D_MODEL) - mean * mean;
    float rstd = rsqrtf(var + 1e-5f);

    int t  = r & (T_LEN - 1);
    int c0 = tid * 4;
    const float* xp = (const float*)&xv;
    float4 hv; float* hp = (float*)&hv;
    __nv_bfloat16 hb[4], lb[4];
    #pragma unroll
    for (int u = 0; u < 4; u++) {
        int c = c0 + u;
        float div = expf((float)(c & ~1) * (-9.2103403719761836f / 512.0f));
        float ang = (float)t * div;
        float pe  = (c & 1) ? cosf(ang) : sinf(ang);
        hp[u] = (xp[u] - mean) * rstd * gam[c] + bet[c] + pe;
        bf16_split(hp[u], hb[u], lb[u]);
    }
    ((float4*)(h_out + (size_t)r * D_MODEL))[tid] = hv;
    size_t base = (size_t)r * D_MODEL + c0;
    *(__nv_bfloat162*)(hh_out + base    ) = __nv_bfloat162(hb[0], hb[1]);
    *(__nv_bfloat162*)(hh_out + base + 2) = __nv_bfloat162(hb[2], hb[3]);
    *(__nv_bfloat162*)(hl_out + base    ) = __nv_bfloat162(lb[0], lb[1]);
    *(__nv_bfloat162*)(hl_out + base + 2) = __nv_bfloat162(lb[2], lb[3]);
}

// ============================================================
// Kernel 2: bf16 MMA GEMM with 2-term compensation.
// MODE 0: fp32 row-major out.
// MODE 1: bf16 split out (scaled by ascale), scatter [B,H,T,64].
// MODE 2: bf16 split out, scatter [B,H,64,T] (transposed, for V).
// ============================================================
template<int MODE>
__global__ __launch_bounds__(256) void gemm_bf16(
    const __nv_bfloat16* __restrict__ Ah, const __nv_bfloat16* __restrict__ Al,
    const __nv_bfloat16* __restrict__ Wh, const __nv_bfloat16* __restrict__ Wl,
    float* __restrict__ C,
    __nv_bfloat16* __restrict__ Ch, __nv_bfloat16* __restrict__ Cl,
    float ascale)
{
    const int K = 512, N = 512;
    __shared__ __nv_bfloat16 sAh[128][40], sAl[128][40];
    __shared__ __nv_bfloat16 sWh[64][40],  sWl[64][40];

    int tid  = threadIdx.x;
    int m0   = blockIdx.y * 128;
    int n0   = blockIdx.x * 64;
    int warp = tid >> 5, lane = tid & 31;
    int wm   = (warp >> 1) * 32;
    int wn   = (warp & 1) * 32;
    int g    = lane >> 2, t = lane & 3;

    float acc[2][4][4];
    #pragma unroll
    for (int i = 0; i < 2; i++)
        #pragma unroll
        for (int j = 0; j < 4; j++)
            #pragma unroll
            for (int e = 0; e < 4; e++) acc[i][j][e] = 0.0f;

    for (int k0 = 0; k0 < K; k0 += 32) {
        __syncthreads();
        #pragma unroll
        for (int i = 0; i < 8; i++) {
            int idx = tid + i * 256;
            int r = idx >> 4, c = (idx & 15) * 2;
            *(uint*)&sAh[r][c] = *(const uint*)(Ah + (size_t)(m0 + r) * K + k0 + c);
            *(uint*)&sAl[r][c] = *(const uint*)(Al + (size_t)(m0 + r) * K + k0 + c);
        }
        #pragma unroll
        for (int i = 0; i < 4; i++) {
            int idx = tid + i * 256;
            int kk = idx >> 5, nn = (idx & 31) * 2;
            __nv_bfloat162 h2 = *(const __nv_bfloat162*)(Wh + (size_t)(k0 + kk) * N + n0 + nn);
            __nv_bfloat162 l2 = *(const __nv_bfloat162*)(Wl + (size_t)(k0 + kk) * N + n0 + nn);
            sWh[nn][kk] = h2.x; sWh[nn + 1][kk] = h2.y;
            sWl[nn][kk] = l2.x; sWl[nn + 1][kk] = l2.y;
        }
        __syncthreads();

        #pragma unroll
        for (int ks = 0; ks < 32; ks += 16) {
            uint ah[2][4], al[2][4], bh[4][2], bl[4][2];
            #pragma unroll
            for (int mt = 0; mt < 2; mt++) {
                int mr = wm + mt * 16;
                ah[mt][0] = *(uint*)&sAh[mr + g    ][ks + t*2    ];
                ah[mt][1] = *(uint*)&sAh[mr + g + 8][ks + t*2    ];
                ah[mt][2] = *(uint*)&sAh[mr + g    ][ks + t*2 + 8];
                ah[mt][3] = *(uint*)&sAh[mr + g + 8][ks + t*2 + 8];
                al[mt][0] = *(uint*)&sAl[mr + g    ][ks + t*2    ];
                al[mt][1] = *(uint*)&sAl[mr + g + 8][ks + t*2    ];
                al[mt][2] = *(uint*)&sAl[mr + g    ][ks + t*2 + 8];
                al[mt][3] = *(uint*)&sAl[mr + g + 8][ks + t*2 + 8];
            }
            #pragma unroll
            for (int nt = 0; nt < 4; nt++) {
                int nr = wn + nt * 8 + g;
                bh[nt][0] = *(uint*)&sWh[nr][ks + t*2    ];
                bh[nt][1] = *(uint*)&sWh[nr][ks + t*2 + 8];
                bl[nt][0] = *(uint*)&sWl[nr][ks + t*2    ];
                bl[nt][1] = *(uint*)&sWl[nr][ks + t*2 + 8];
            }
            #pragma unroll
            for (int mt = 0; mt < 2; mt++)
                #pragma unroll
                for (int nt = 0; nt < 4; nt++) {
                    mma_bf16(acc[mt][nt], ah[mt], bh[nt]);
                    mma_bf16(acc[mt][nt], ah[mt], bl[nt]);
                    mma_bf16(acc[mt][nt], al[mt], bh[nt]);
                }
        }
    }

    #pragma unroll
    for (int mt = 0; mt < 2; mt++)
        #pragma unroll
        for (int nt = 0; nt < 4; nt++) {
            float* a = acc[mt][nt];
            int m = m0 + wm + mt * 16 + g;
            int n = n0 + wn + nt * 8 + t * 2;
            if (MODE == 0) {
                *(float2*)(C + (size_t)m * N + n)       = make_float2(a[0], a[1]);
                *(float2*)(C + (size_t)(m + 8) * N + n) = make_float2(a[2], a[3]);
            } else {
                #pragma unroll
                for (int e = 0; e < 4; e++) {
                    int mm = m + (e >> 1) * 8;
                    int nn = n + (e & 1);
                    int bb = mm >> 11, tt = mm & (T_LEN - 1);
                    int hh = nn >> 6,  dd = nn & 63;
                    size_t addr;
                    if (MODE == 1)
                        addr = (((size_t)bb * N_HEADS + hh) * T_LEN + tt) * D_K + dd;
                    else
                        addr = (((size_t)bb * N_HEADS + hh) * D_K + dd) * T_LEN + tt;
                    __nv_bfloat16 hv, lv;
                    bf16_split(a[e] * ascale, hv, lv);
                    Ch[addr] = hv;
                    Cl[addr] = lv;
                }
            }
        }
}

// ============================================================
// Kernel 3: bf16 MMA causal flash attention.
// grid (32 q-blocks reversed, 32 bh), 128 threads = 4 warps, m16/warp.
// Q pre-scaled by 0.125 in the projection epilogue.
// Compensated: S = QhKh + QhKl + QlKh ; O = PhVh + PhVl + PlVh.
// ============================================================
__global__ __launch_bounds__(128) void attn_mma(
    const __nv_bfloat16* __restrict__ qh_in, const __nv_bfloat16* __restrict__ ql_in,
    const __nv_bfloat16* __restrict__ kh_in, const __nv_bfloat16* __restrict__ kl_in,
    const __nv_bfloat16* __restrict__ vh_in, const __nv_bfloat16* __restrict__ vl_in,
    __nv_bfloat16* __restrict__ oh_out, __nv_bfloat16* __restrict__ ol_out)
{
    int qb   = (int)gridDim.x - 1 - (int)blockIdx.x;   // big blocks first
    int bh   = blockIdx.y;
    int b    = bh >> 3, h = bh & 7;
    int warp = threadIdx.x >> 5, lane = threadIdx.x & 31;
    int g    = lane >> 2, t = lane & 3;
    int q0   = qb * 64 + warp * 16;

    __shared__ __nv_bfloat16 sKh[64][72], sKl[64][72];   // [kv][d]
    __shared__ __nv_bfloat16 sVh[64][72], sVl[64][72];   // [d][kv]

    // ---- Q fragments (registers, whole kernel) ----
    uint qfh[4][4], qfl[4][4];
    {
        const size_t qb0 = (size_t)bh * T_LEN * D_K;
        #pragma unroll
        for (int c = 0; c < 4; c++)
            #pragma unroll
            for (int p = 0; p < 4; p++) {
                int row = q0 + g + (p & 1) * 8;
                int col = c * 16 + t * 2 + (p >> 1) * 8;
                qfh[c][p] = *(const uint*)(qh_in + qb0 + (size_t)row * D_K + col);
                qfl[c][p] = *(const uint*)(ql_in + qb0 + (size_t)row * D_K + col);
            }
    }

    float o_[8][4];
    #pragma unroll
    for (int j = 0; j < 8; j++)
        #pragma unroll
        for (int e = 0; e < 4; e++) o_[j][e] = 0.0f;
    float mrow0 = -1e30f, mrow1 = -1e30f, lrow0 = 0.0f, lrow1 = 0.0f;

    int tr = threadIdx.x >> 1;
    int tc = (threadIdx.x & 1) * 32;

    int ntiles = qb + 1;
    for (int kt = 0; kt < ntiles; kt++) {
        int kv0 = kt * 64;
        __syncthreads();
        {
            const size_t kb = ((size_t)bh * T_LEN + kv0 + tr) * D_K + tc;
            const size_t vb = ((size_t)bh * D_K + tr) * T_LEN + kv0 + tc;
            #pragma unroll
            for (int i = 0; i < 4; i++) {
                *(uint4*)&sKh[tr][tc + i * 8] = *(const uint4*)(kh_in + kb + i * 8);
                *(uint4*)&sKl[tr][tc + i * 8] = *(const uint4*)(kl_in + kb + i * 8);
                *(uint4*)&sVh[tr][tc + i * 8] = *(const uint4*)(vh_in + vb + i * 8);
                *(uint4*)&sVl[tr][tc + i * 8] = *(const uint4*)(vl_in + vb + i * 8);
            }
        }
        __syncthreads();

        // ---- S = Q K^T ----
        float s[8][4];
        #pragma unroll
        for (int j = 0; j < 8; j++)
            #pragma unroll
            for (int e = 0; e < 4; e++) s[j][e] = 0.0f;

        #pragma unroll
        for (int c = 0; c < 4; c++)
            #pragma unroll
            for (int j = 0; j < 8; j++) {
                uint bhv[2], blv[2];
                bhv[0] = *(uint*)&sKh[8*j + g][c*16 + t*2];
                bhv[1] = *(uint*)&sKh[8*j + g][c*16 + t*2 + 8];
                blv[0] = *(uint*)&sKl[8*j + g][c*16 + t*2];
                blv[1] = *(uint*)&sKl[8*j + g][c*16 + t*2 + 8];
                mma_bf16(s[j], qfh[c], bhv);
                mma_bf16(s[j], qfh[c], blv);
                mma_bf16(s[j], qfl[c], bhv);
            }

        // ---- causal mask on diagonal tile ----
        if (kt == qb) {
            #pragma unroll
            for (int j = 0; j < 8; j++)
                #pragma unroll
                for (int e = 0; e < 4; e++) {
                    int col = 8*j + t*2 + (e & 1);
                    int row = warp*16 + g + (e >> 1) * 8;
                    if (col > row) s[j][e] = -1e30f;
                }
        }

        // ---- online softmax ----
        float mx0 = -1e30f, mx1 = -1e30f;
        #pragma unroll
        for (int j = 0; j < 8; j++) {
            mx0 = fmaxf(mx0, fmaxf(s[j][0], s[j][1]));
            mx1 = fmaxf(mx1, fmaxf(s[j][2], s[j][3]));
        }
        mx0 = fmaxf(mx0, __shfl_xor_sync(0xffffffffu, mx0, 1));
        mx0 = fmaxf(mx0, __shfl_xor_sync(0xffffffffu, mx0, 2));
        mx1 = fmaxf(mx1, __shfl_xor_sync(0xffffffffu, mx1, 1));
        mx1 = fmaxf(mx1, __shfl_xor_sync(0xffffffffu, mx1, 2));

        float nm0 = fmaxf(mrow0, mx0), nm1 = fmaxf(mrow1, mx1);
        float sc0 = __expf(mrow0 - nm0), sc1 = __expf(mrow1 - nm1);
        mrow0 = nm0; mrow1 = nm1;
        lrow0 *= sc0; lrow1 *= sc1;
        #pragma unroll
        for (int j = 0; j < 8; j++) {
            o_[j][0] *= sc0; o_[j][1] *= sc0;
            o_[j][2] *= sc1; o_[j][3] *= sc1;
        }

        float p[8][4];
        #pragma unroll
        for (int j = 0; j < 8; j++) {
            p[j][0] = __expf(s[j][0] - nm0);
            p[j][1] = __expf(s[j][1] - nm0);
            p[j][2] = __expf(s[j][2] - nm1);
            p[j][3] = __expf(s[j][3] - nm1);
            lrow0 += p[j][0] + p[j][1];
            lrow1 += p[j][2] + p[j][3];
        }

        // ---- pack P into A-fragments (register-only) ----
        uint pfh[4][4], pfl[4][4];
        #pragma unroll
        for (int c2 = 0; c2 < 4; c2++) {
            int j0 = 2*c2, j1 = 2*c2 + 1;
            pfh[c2][0] = packbf(p[j0][0], p[j0][1]);
            pfh[c2][1] = packbf(p[j0][2], p[j0][3]);
            pfh[c2][2] = packbf(p[j1][0], p[j1][1]);
            pfh[c2][3] = packbf(p[j1][2], p[j1][3]);
            pfl[c2][0] = packbf(p[j0][0] - lo16f(pfh[c2][0]), p[j0][1] - hi16f(pfh[c2][0]));
            pfl[c2][1] = packbf(p[j0][2] - lo16f(pfh[c2][1]), p[j0][3] - hi16f(pfh[c2][1]));
            pfl[c2][2] = packbf(p[j1][0] - lo16f(pfh[c2][2]), p[j1][1] - hi16f(pfh[c2][2]));
            pfl[c2][3] = packbf(p[j1][2] - lo16f(pfh[c2][3]), p[j1][3] - hi16f(pfh[c2][3]));
        }

        // ---- O += P V ----
        #pragma unroll
        for (int c2 = 0; c2 < 4; c2++)
            #pragma unroll
            for (int j = 0; j < 8; j++) {
                uint bhv[2], blv[2];
                bhv[0] = *(uint*)&sVh[8*j + g][c2*16 + t*2];
                bhv[1] = *(uint*)&sVh[8*j + g][c2*16 + t*2 + 8];
                blv[0] = *(uint*)&sVl[8*j + g][c2*16 + t*2];
                blv[1] = *(uint*)&sVl[8*j + g][c2*16 + t*2 + 8];
                mma_bf16(o_[j], pfh[c2], bhv);
                mma_bf16(o_[j], pfh[c2], blv);
                mma_bf16(o_[j], pfl[c2], bhv);
            }
    }

    // ---- finalize ----
    lrow0 += __shfl_xor_sync(0xffffffffu, lrow0, 1);
    lrow0 += __shfl_xor_sync(0xffffffffu, lrow0, 2);
    lrow1 += __shfl_xor_sync(0xffffffffu, lrow1, 1);
    lrow1 += __shfl_xor_sync(0xffffffffu, lrow1, 2);
    float inv0 = 1.0f / lrow0, inv1 = 1.0f / lrow1;

    int row0 = q0 + g, row1 = q0 + g + 8;
    size_t ob0 = ((size_t)b * T_LEN + row0) * D_MODEL + h * D_K;
    size_t ob1 = ((size_t)b * T_LEN + row1) * D_MODEL + h * D_K;
    #pragma unroll
    for (int j = 0; j < 8; j++) {
        int col = 8*j + t*2;
        float v00 = o_[j][0] * inv0, v01 = o_[j][1] * inv0;
        float v10 = o_[j][2] * inv1, v11 = o_[j][3] * inv1;
        __nv_bfloat16 h00, l00, h01, l01, h10, l10, h11, l11;
        bf16_split(v00, h00, l00); bf16_split(v01, h01, l01);
        bf16_split(v10, h10, l10); bf16_split(v11, h11, l11);
        *(__nv_bfloat162*)(oh_out + ob0 + col) = __nv_bfloat162(h00, h01);
        *(__nv_bfloat162*)(ol_out + ob0 + col) = __nv_bfloat162(l00, l01);
        *(__nv_bfloat162*)(oh_out + ob1 + col) = __nv_bfloat162(h10, h11);
        *(__nv_bfloat162*)(ol_out + ob1 + col) = __nv_bfloat162(l10, l11);
    }
}

// ============================================================
// Kernel 4: residual + LN(eps 1e-6) + outer residual
// ============================================================
__global__ __launch_bounds__(128) void ln2_kernel(
    const float* __restrict__ y,
    const float* __restrict__ h,
    const float* __restrict__ x,
    const float* __restrict__ g2,
    const float* __restrict__ b2,
    float* __restrict__ out)
{
    int r   = blockIdx.x;
    int tid = threadIdx.x;
    float4 yv = ((const float4*)(y + (size_t)r * D_MODEL))[tid];
    float4 hv = ((const float4*)(h + (size_t)r * D_MODEL))[tid];
    float4 tv;
    tv.x = yv.x + hv.x; tv.y = yv.y + hv.y;
    tv.z = yv.z + hv.z; tv.w = yv.w + hv.w;

    float sum = tv.x + tv.y + tv.z + tv.w;
    float sq  = tv.x*tv.x + tv.y*tv.y + tv.z*tv.z + tv.w*tv.w;
    #pragma unroll
    for (int off = 16; off; off >>= 1) {
        sum += __shfl_xor_sync(0xffffffffu, sum, off);
        sq  += __shfl_xor_sync(0xffffffffu, sq,  off);
    }
    __shared__ float s1[4], s2[4];
    if ((tid & 31) == 0) { s1[tid >> 5] = sum; s2[tid >> 5] = sq; }
    __syncthreads();
    sum = s1[0] + s1[1] + s1[2] + s1[3];
    sq  = s2[0] + s2[1] + s2[2] + s2[3];

    float mean = sum * (1.0f / D_MODEL);
    float var  = sq  * (1.0f / D_MODEL) - mean * mean;
    float rstd = rsqrtf(var + 1e-6f);

    float4 xv = ((const float4*)(x + (size_t)r * D_MODEL))[tid];
    const float* tp = (const float*)&tv;
    const float* xp = (const float*)&xv;
    int c0 = tid * 4;
    float4 ov; float* op = (float*)&ov;
    #pragma unroll
    for (int u = 0; u < 4; u++) {
        int c = c0 + u;
        op[u] = (tp[u] - mean) * rstd * g2[c] + b2[c] + xp[u];
    }
    ((float4*)(out + (size_t)r * D_MODEL))[tid] = ov;
}

// ============================================================
// launch
// ============================================================
extern "C" void kernel_launch(void* const* d_in, const int* in_sizes, int n_in,
                              void* d_out, int out_size)
{
    const float* x   = (const float*)d_in[0];
    const float* g1  = (const float*)d_in[1];
    const float* b1  = (const float*)d_in[2];
    const float* wq  = (const float*)d_in[3];
    const float* wk  = (const float*)d_in[4];
    const float* wv  = (const float*)d_in[5];
    const float* wfc = (const float*)d_in[6];
    const float* g2  = (const float*)d_in[7];
    const float* b2  = (const float*)d_in[8];
    float* out = (float*)d_out;

    float *ph, *py;
    __nv_bfloat16 *phh, *phl, *pqh, *pql, *pkh, *pkl, *pvh, *pvl, *poh, *pol, *pwh, *pwl;
    cudaGetSymbolAddress((void**)&ph,  g_h);
    cudaGetSymbolAddress((void**)&phh, g_hh);
    cudaGetSymbolAddress((void**)&phl, g_hl);
    cudaGetSymbolAddress((void**)&pqh, g_qh);
    cudaGetSymbolAddress((void**)&pql, g_ql);
    cudaGetSymbolAddress((void**)&pkh, g_kh);
    cudaGetSymbolAddress((void**)&pkl, g_kl);
    cudaGetSymbolAddress((void**)&pvh, g_vh);
    cudaGetSymbolAddress((void**)&pvl, g_vl);
    cudaGetSymbolAddress((void**)&poh, g_oh);
    cudaGetSymbolAddress((void**)&pol, g_ol);
    cudaGetSymbolAddress((void**)&py,  g_y);
    cudaGetSymbolAddress((void**)&pwh, g_wh);
    cudaGetSymbolAddress((void**)&pwl, g_wl);

    const int WSZ = D_MODEL * D_MODEL;
    split_w_kernel<<<dim3(WSZ / 256, 4), 256>>>(wq, wk, wv, wfc, pwh, pwl);

    ln1_pe_kernel<<<NROWS, 128>>>(x, g1, b1, ph, phh, phl);

    dim3 gg(D_MODEL / 64, NROWS / 128);   // (8, 64)
    gemm_bf16<1><<<gg, 256>>>(phh, phl, pwh + 0 * WSZ, pwl + 0 * WSZ, nullptr, pqh, pql, 0.125f);
    gemm_bf16<1><<<gg, 256>>>(phh, phl, pwh + 1 * WSZ, pwl + 1 * WSZ, nullptr, pkh, pkl, 1.0f);
    gemm_bf16<2><<<gg, 256>>>(phh, phl, pwh + 2 * WSZ, pwl + 2 * WSZ, nullptr, pvh, pvl, 1.0f);

    attn_mma<<<dim3(T_LEN / 64, BATCH * N_HEADS), 128>>>(
        pqh, pql, pkh, pkl, pvh, pvl, poh, pol);

    gemm_bf16<0><<<gg, 256>>>(poh, pol, pwh + 3 * WSZ, pwl + 3 * WSZ, py, nullptr, nullptr, 1.0f);

    ln2_kernel<<<NROWS, 128>>>(py, ph, x, g2, b2, out);
}

// round 14
// speedup vs baseline: 3.5989x; 1.4944x over previous
#include <cuda_runtime.h>
#include <cuda_bf16.h>
#include <math.h>

#define D_MODEL 512
#define T_LEN   2048
#define BATCH   4
#define NROWS   (BATCH * T_LEN)   // 8192
#define N_HEADS 8
#define D_K     64

typedef unsigned int uint;

// -------- scratch --------
__device__ float          g_h  [NROWS * D_MODEL];  // LN1(x)+PE fp32 (residual1)
__device__ __nv_bfloat16  g_hh [NROWS * D_MODEL];
__device__ __nv_bfloat16  g_hl [NROWS * D_MODEL];
__device__ __nv_bfloat16  g_qh [NROWS * D_MODEL];  // [B,H,T,64]  (pre-scaled by 0.125)
__device__ __nv_bfloat16  g_ql [NROWS * D_MODEL];
__device__ __nv_bfloat16  g_kh [NROWS * D_MODEL];  // [B,H,T,64]
__device__ __nv_bfloat16  g_kl [NROWS * D_MODEL];
__device__ __nv_bfloat16  g_vh [NROWS * D_MODEL];  // [B,H,64,T]  (transposed)
__device__ __nv_bfloat16  g_vl [NROWS * D_MODEL];
__device__ __nv_bfloat16  g_oh [NROWS * D_MODEL];  // attn out [B,T,512]
__device__ __nv_bfloat16  g_ol [NROWS * D_MODEL];
__device__ float          g_y  [NROWS * D_MODEL];
__device__ __nv_bfloat16  g_wh [4 * D_MODEL * D_MODEL];  // W^T [n][k], hi
__device__ __nv_bfloat16  g_wl [4 * D_MODEL * D_MODEL];  // W^T [n][k], lo

__device__ __forceinline__ void bf16_split(float x, __nv_bfloat16& h, __nv_bfloat16& l) {
    h = __float2bfloat16(x);
    l = __float2bfloat16(x - __bfloat162float(h));
}
__device__ __forceinline__ uint packbf(float lo, float hi) {
    uint r;
    asm("cvt.rn.bf16x2.f32 %0, %1, %2;" : "=r"(r) : "f"(hi), "f"(lo));
    return r;
}
__device__ __forceinline__ float lo16f(uint u) { return __uint_as_float(u << 16); }
__device__ __forceinline__ float hi16f(uint u) { return __uint_as_float(u & 0xffff0000u); }

__device__ __forceinline__ void mma_bf16(float* d, const uint* a, const uint* b) {
    asm volatile(
        "mma.sync.aligned.m16n8k16.row.col.f32.bf16.bf16.f32 "
        "{%0,%1,%2,%3},{%4,%5,%6,%7},{%8,%9},{%0,%1,%2,%3};\n"
        : "+f"(d[0]), "+f"(d[1]), "+f"(d[2]), "+f"(d[3])
        : "r"(a[0]), "r"(a[1]), "r"(a[2]), "r"(a[3]), "r"(b[0]), "r"(b[1]));
}
__device__ __forceinline__ void ldsm4(uint* r, uint addr) {
    asm volatile("ldmatrix.sync.aligned.m8n8.x4.shared.b16 {%0,%1,%2,%3}, [%4];"
        : "=r"(r[0]), "=r"(r[1]), "=r"(r[2]), "=r"(r[3]) : "r"(addr));
}
__device__ __forceinline__ void cp_async16(uint dst, const void* src) {
    asm volatile("cp.async.cg.shared.global [%0], [%1], 16;" :: "r"(dst), "l"(src));
}
__device__ __forceinline__ void cp_commit() { asm volatile("cp.async.commit_group;"); }
template<int N> __device__ __forceinline__ void cp_wait() {
    asm volatile("cp.async.wait_group %0;" :: "n"(N));
}

// ============================================================
// Weight split + transpose: w[k][n] fp32 -> wh/wl[n][k] bf16
// block (32,8), 32x32 tiles via smem
// ============================================================
__global__ __launch_bounds__(256) void split_w_kernel(
    const float* __restrict__ w0, const float* __restrict__ w1,
    const float* __restrict__ w2, const float* __restrict__ w3,
    __nv_bfloat16* __restrict__ wh, __nv_bfloat16* __restrict__ wl)
{
    const int WSZ = D_MODEL * D_MODEL;
    __shared__ float tile[32][33];
    int wsel = blockIdx.z;
    const float* w = (wsel == 0) ? w0 : (wsel == 1) ? w1 : (wsel == 2) ? w2 : w3;
    int n0 = blockIdx.x * 32, k0 = blockIdx.y * 32;
    int tx = threadIdx.x, ty = threadIdx.y;
    #pragma unroll
    for (int j = 0; j < 32; j += 8)
        tile[ty + j][tx] = w[(size_t)(k0 + ty + j) * D_MODEL + n0 + tx];
    __syncthreads();
    #pragma unroll
    for (int j = 0; j < 32; j += 8) {
        float v = tile[tx][ty + j];
        __nv_bfloat16 h, l;
        bf16_split(v, h, l);
        size_t o = (size_t)wsel * WSZ + (size_t)(n0 + ty + j) * D_MODEL + k0 + tx;
        wh[o] = h; wl[o] = l;
    }
}

// ============================================================
// Kernel 1: LN(eps 1e-5) + sinusoidal PE -> fp32 + bf16 split
// ============================================================
__global__ __launch_bounds__(128) void ln1_pe_kernel(
    const float* __restrict__ x,
    const float* __restrict__ gam,
    const float* __restrict__ bet,
    float* __restrict__ h_out,
    __nv_bfloat16* __restrict__ hh_out,
    __nv_bfloat16* __restrict__ hl_out)
{
    int r   = blockIdx.x;
    int tid = threadIdx.x;
    const float4 xv = ((const float4*)(x + (size_t)r * D_MODEL))[tid];

    float sum = xv.x + xv.y + xv.z + xv.w;
    float sq  = xv.x*xv.x + xv.y*xv.y + xv.z*xv.z + xv.w*xv.w;
    #pragma unroll
    for (int off = 16; off; off >>= 1) {
        sum += __shfl_xor_sync(0xffffffffu, sum, off);
        sq  += __shfl_xor_sync(0xffffffffu, sq,  off);
    }
    __shared__ float s1[4], s2[4];
    if ((tid & 31) == 0) { s1[tid >> 5] = sum; s2[tid >> 5] = sq; }
    __syncthreads();
    sum = s1[0] + s1[1] + s1[2] + s1[3];
    sq  = s2[0] + s2[1] + s2[2] + s2[3];

    float mean = sum * (1.0f / D_MODEL);
    float var  = sq  * (1.0f / D_MODEL) - mean * mean;
    float rstd = rsqrtf(var + 1e-5f);

    int t  = r & (T_LEN - 1);
    int c0 = tid * 4;
    const float* xp = (const float*)&xv;
    float4 hv; float* hp = (float*)&hv;
    __nv_bfloat16 hb[4], lb[4];
    #pragma unroll
    for (int u = 0; u < 4; u++) {
        int c = c0 + u;
        float div = expf((float)(c & ~1) * (-9.2103403719761836f / 512.0f));
        float ang = (float)t * div;
        float pe  = (c & 1) ? cosf(ang) : sinf(ang);
        hp[u] = (xp[u] - mean) * rstd * gam[c] + bet[c] + pe;
        bf16_split(hp[u], hb[u], lb[u]);
    }
    ((float4*)(h_out + (size_t)r * D_MODEL))[tid] = hv;
    size_t base = (size_t)r * D_MODEL + c0;
    *(__nv_bfloat162*)(hh_out + base    ) = __nv_bfloat162(hb[0], hb[1]);
    *(__nv_bfloat162*)(hh_out + base + 2) = __nv_bfloat162(hb[2], hb[3]);
    *(__nv_bfloat162*)(hl_out + base    ) = __nv_bfloat162(lb[0], lb[1]);
    *(__nv_bfloat162*)(hl_out + base + 2) = __nv_bfloat162(lb[2], lb[3]);
}

// ============================================================
// Kernel 2: bf16 MMA GEMM, 2-stage cp.async pipeline + ldmatrix.
// A [M][K] row-major, W^T [N][K] row-major. 2-term compensation.
// BM=128 BN=64 BK=32, 256 threads, 2 CTAs/SM.
// MODE 0: fp32 row-major. MODE 1: bf16 split [B,H,T,64] (×ascale).
// MODE 2: bf16 split [B,H,64,T].
// ============================================================
#define BM 128
#define BN 64
#define BK 32
#define AST 40                    // row stride elems (80B = 5x16B)
#define A_STAGE (BM * AST)        // 5120 elems
#define W_STAGE (BN * AST)        // 2560 elems
#define GEMM_SMEM ((2 * A_STAGE * 2 + 2 * W_STAGE * 2) * 2)  // bytes = 61440

template<int MODE>
__global__ __launch_bounds__(256, 2) void gemm_bf16(
    const __nv_bfloat16* __restrict__ Ah, const __nv_bfloat16* __restrict__ Al,
    const __nv_bfloat16* __restrict__ Wh, const __nv_bfloat16* __restrict__ Wl,
    float* __restrict__ C,
    __nv_bfloat16* __restrict__ Ch, __nv_bfloat16* __restrict__ Cl,
    float ascale)
{
    const int K = 512, N = 512;
    extern __shared__ __nv_bfloat16 smem[];
    __nv_bfloat16* pAh = smem;                        // [2][BM][AST]
    __nv_bfloat16* pAl = pAh + 2 * A_STAGE;
    __nv_bfloat16* pWh = pAl + 2 * A_STAGE;           // [2][BN][AST]
    __nv_bfloat16* pWl = pWh + 2 * W_STAGE;

    uint bAh = (uint)__cvta_generic_to_shared(pAh);
    uint bAl = (uint)__cvta_generic_to_shared(pAl);
    uint bWh = (uint)__cvta_generic_to_shared(pWh);
    uint bWl = (uint)__cvta_generic_to_shared(pWl);

    int tid  = threadIdx.x;
    int m0   = blockIdx.y * BM;
    int n0   = blockIdx.x * BN;
    int warp = tid >> 5, lane = tid & 31;
    int wm   = (warp >> 1) * 32;
    int wn   = (warp & 1) * 32;
    int g    = lane >> 2, t = lane & 3;

    // cp.async source/dst indices
    int ar = tid >> 2;              // A row (first half), +64 for second
    int ac = (tid & 3) << 3;        // col in elems {0,8,16,24}
    const size_t gAoff0 = (size_t)(m0 + ar) * K + ac;
    const size_t gAoff1 = (size_t)(m0 + ar + 64) * K + ac;
    const size_t gWoff  = (size_t)(n0 + ar) * K + ac;   // ar<64 covers W rows
    const uint sAoff0 = (ar * AST + ac) * 2;
    const uint sAoff1 = ((ar + 64) * AST + ac) * 2;
    const uint sWoff  = (ar * AST + ac) * 2;

    // ldmatrix row offsets (elems, before *2 bytes)
    const int aRow = (wm + (lane & 15)) * AST + ((lane >> 4) << 3);
    const int bRow = (wn + (lane & 7) + ((lane >> 4) << 3)) * AST + (((lane >> 3) & 1) << 3);

    float acc[2][4][4];
    #pragma unroll
    for (int i = 0; i < 2; i++)
        #pragma unroll
        for (int j = 0; j < 4; j++)
            #pragma unroll
            for (int e = 0; e < 4; e++) acc[i][j][e] = 0.0f;

    // ---- issue stage copies ----
    auto issue = [&](int k0, int st) {
        uint sa = st * A_STAGE * 2, sw = st * W_STAGE * 2;
        cp_async16(bAh + sa + sAoff0, Ah + gAoff0 + k0);
        cp_async16(bAh + sa + sAoff1, Ah + gAoff1 + k0);
        cp_async16(bAl + sa + sAoff0, Al + gAoff0 + k0);
        cp_async16(bAl + sa + sAoff1, Al + gAoff1 + k0);
        cp_async16(bWh + sw + sWoff, Wh + gWoff + k0);
        cp_async16(bWl + sw + sWoff, Wl + gWoff + k0);
    };

    issue(0, 0); cp_commit();
    const int NT = K / BK;  // 16
    for (int it = 0; it < NT; it++) {
        int st = it & 1;
        if (it + 1 < NT) { issue((it + 1) * BK, st ^ 1); cp_commit(); cp_wait<1>(); }
        else             { cp_wait<0>(); }
        __syncthreads();

        uint sa = st * A_STAGE * 2, sw = st * W_STAGE * 2;
        #pragma unroll
        for (int ks = 0; ks < BK; ks += 16) {
            uint a_h[2][4], a_l[2][4], b_h[2][4], b_l[2][4];
            #pragma unroll
            for (int mt = 0; mt < 2; mt++) {
                uint off = sa + (aRow + mt * 16 * AST + ks) * 2;
                ldsm4(a_h[mt], bAh + off);
                ldsm4(a_l[mt], bAl + off);
            }
            #pragma unroll
            for (int nt2 = 0; nt2 < 2; nt2++) {
                uint off = sw + (bRow + nt2 * 16 * AST + ks) * 2;
                ldsm4(b_h[nt2], bWh + off);
                ldsm4(b_l[nt2], bWl + off);
            }
            #pragma unroll
            for (int mt = 0; mt < 2; mt++)
                #pragma unroll
                for (int nt = 0; nt < 4; nt++) {
                    const uint* bh = &b_h[nt >> 1][(nt & 1) * 2];
                    const uint* bl = &b_l[nt >> 1][(nt & 1) * 2];
                    mma_bf16(acc[mt][nt], a_h[mt], bh);
                    mma_bf16(acc[mt][nt], a_h[mt], bl);
                    mma_bf16(acc[mt][nt], a_l[mt], bh);
                }
        }
        __syncthreads();
    }

    // ---- epilogue ----
    #pragma unroll
    for (int mt = 0; mt < 2; mt++)
        #pragma unroll
        for (int nt = 0; nt < 4; nt++) {
            float* a = acc[mt][nt];
            int m = m0 + wm + mt * 16 + g;
            int n = n0 + wn + nt * 8 + t * 2;
            if (MODE == 0) {
                *(float2*)(C + (size_t)m * N + n)       = make_float2(a[0], a[1]);
                *(float2*)(C + (size_t)(m + 8) * N + n) = make_float2(a[2], a[3]);
            } else if (MODE == 1) {
                #pragma unroll
                for (int half = 0; half < 2; half++) {
                    int mm = m + half * 8;
                    int bb = mm >> 11, tt = mm & (T_LEN - 1);
                    int hh = n >> 6,  dd = n & 63;
                    size_t addr = (((size_t)bb * N_HEADS + hh) * T_LEN + tt) * D_K + dd;
                    __nv_bfloat16 h0, l0, h1, l1;
                    bf16_split(a[half*2+0] * ascale, h0, l0);
                    bf16_split(a[half*2+1] * ascale, h1, l1);
                    *(__nv_bfloat162*)(Ch + addr) = __nv_bfloat162(h0, h1);
                    *(__nv_bfloat162*)(Cl + addr) = __nv_bfloat162(l0, l1);
                }
            } else {
                #pragma unroll
                for (int e = 0; e < 4; e++) {
                    int mm = m + (e >> 1) * 8;
                    int nn = n + (e & 1);
                    int bb = mm >> 11, tt = mm & (T_LEN - 1);
                    int hh = nn >> 6,  dd = nn & 63;
                    size_t addr = (((size_t)bb * N_HEADS + hh) * D_K + dd) * T_LEN + tt;
                    __nv_bfloat16 hv, lv;
                    bf16_split(a[e] * ascale, hv, lv);
                    Ch[addr] = hv;
                    Cl[addr] = lv;
                }
            }
        }
}

// ============================================================
// Kernel 3: bf16 MMA causal flash attention (unchanged from R9).
// ============================================================
__global__ __launch_bounds__(128) void attn_mma(
    const __nv_bfloat16* __restrict__ qh_in, const __nv_bfloat16* __restrict__ ql_in,
    const __nv_bfloat16* __restrict__ kh_in, const __nv_bfloat16* __restrict__ kl_in,
    const __nv_bfloat16* __restrict__ vh_in, const __nv_bfloat16* __restrict__ vl_in,
    __nv_bfloat16* __restrict__ oh_out, __nv_bfloat16* __restrict__ ol_out)
{
    int qb   = (int)gridDim.x - 1 - (int)blockIdx.x;   // big blocks first
    int bh   = blockIdx.y;
    int b    = bh >> 3, h = bh & 7;
    int warp = threadIdx.x >> 5, lane = threadIdx.x & 31;
    int g    = lane >> 2, t = lane & 3;
    int q0   = qb * 64 + warp * 16;

    __shared__ __nv_bfloat16 sKh[64][72], sKl[64][72];   // [kv][d]
    __shared__ __nv_bfloat16 sVh[64][72], sVl[64][72];   // [d][kv]

    uint qfh[4][4], qfl[4][4];
    {
        const size_t qb0 = (size_t)bh * T_LEN * D_K;
        #pragma unroll
        for (int c = 0; c < 4; c++)
            #pragma unroll
            for (int p = 0; p < 4; p++) {
                int row = q0 + g + (p & 1) * 8;
                int col = c * 16 + t * 2 + (p >> 1) * 8;
                qfh[c][p] = *(const uint*)(qh_in + qb0 + (size_t)row * D_K + col);
                qfl[c][p] = *(const uint*)(ql_in + qb0 + (size_t)row * D_K + col);
            }
    }

    float o_[8][4];
    #pragma unroll
    for (int j = 0; j < 8; j++)
        #pragma unroll
        for (int e = 0; e < 4; e++) o_[j][e] = 0.0f;
    float mrow0 = -1e30f, mrow1 = -1e30f, lrow0 = 0.0f, lrow1 = 0.0f;

    int tr = threadIdx.x >> 1;
    int tc = (threadIdx.x & 1) * 32;

    int ntiles = qb + 1;
    for (int kt = 0; kt < ntiles; kt++) {
        int kv0 = kt * 64;
        __syncthreads();
        {
            const size_t kb = ((size_t)bh * T_LEN + kv0 + tr) * D_K + tc;
            const size_t vb = ((size_t)bh * D_K + tr) * T_LEN + kv0 + tc;
            #pragma unroll
            for (int i = 0; i < 4; i++) {
                *(uint4*)&sKh[tr][tc + i * 8] = *(const uint4*)(kh_in + kb + i * 8);
                *(uint4*)&sKl[tr][tc + i * 8] = *(const uint4*)(kl_in + kb + i * 8);
                *(uint4*)&sVh[tr][tc + i * 8] = *(const uint4*)(vh_in + vb + i * 8);
                *(uint4*)&sVl[tr][tc + i * 8] = *(const uint4*)(vl_in + vb + i * 8);
            }
        }
        __syncthreads();

        float s[8][4];
        #pragma unroll
        for (int j = 0; j < 8; j++)
            #pragma unroll
            for (int e = 0; e < 4; e++) s[j][e] = 0.0f;

        #pragma unroll
        for (int c = 0; c < 4; c++)
            #pragma unroll
            for (int j = 0; j < 8; j++) {
                uint bhv[2], blv[2];
                bhv[0] = *(uint*)&sKh[8*j + g][c*16 + t*2];
                bhv[1] = *(uint*)&sKh[8*j + g][c*16 + t*2 + 8];
                blv[0] = *(uint*)&sKl[8*j + g][c*16 + t*2];
                blv[1] = *(uint*)&sKl[8*j + g][c*16 + t*2 + 8];
                mma_bf16(s[j], qfh[c], bhv);
                mma_bf16(s[j], qfh[c], blv);
                mma_bf16(s[j], qfl[c], bhv);
            }

        if (kt == qb) {
            #pragma unroll
            for (int j = 0; j < 8; j++)
                #pragma unroll
                for (int e = 0; e < 4; e++) {
                    int col = 8*j + t*2 + (e & 1);
                    int row = warp*16 + g + (e >> 1) * 8;
                    if (col > row) s[j][e] = -1e30f;
                }
        }

        float mx0 = -1e30f, mx1 = -1e30f;
        #pragma unroll
        for (int j = 0; j < 8; j++) {
            mx0 = fmaxf(mx0, fmaxf(s[j][0], s[j][1]));
            mx1 = fmaxf(mx1, fmaxf(s[j][2], s[j][3]));
        }
        mx0 = fmaxf(mx0, __shfl_xor_sync(0xffffffffu, mx0, 1));
        mx0 = fmaxf(mx0, __shfl_xor_sync(0xffffffffu, mx0, 2));
        mx1 = fmaxf(mx1, __shfl_xor_sync(0xffffffffu, mx1, 1));
        mx1 = fmaxf(mx1, __shfl_xor_sync(0xffffffffu, mx1, 2));

        float nm0 = fmaxf(mrow0, mx0), nm1 = fmaxf(mrow1, mx1);
        float sc0 = __expf(mrow0 - nm0), sc1 = __expf(mrow1 - nm1);
        mrow0 = nm0; mrow1 = nm1;
        lrow0 *= sc0; lrow1 *= sc1;
        #pragma unroll
        for (int j = 0; j < 8; j++) {
            o_[j][0] *= sc0; o_[j][1] *= sc0;
            o_[j][2] *= sc1; o_[j][3] *= sc1;
        }

        float p[8][4];
        #pragma unroll
        for (int j = 0; j < 8; j++) {
            p[j][0] = __expf(s[j][0] - nm0);
            p[j][1] = __expf(s[j][1] - nm0);
            p[j][2] = __expf(s[j][2] - nm1);
            p[j][3] = __expf(s[j][3] - nm1);
            lrow0 += p[j][0] + p[j][1];
            lrow1 += p[j][2] + p[j][3];
        }

        uint pfh[4][4], pfl[4][4];
        #pragma unroll
        for (int c2 = 0; c2 < 4; c2++) {
            int j0 = 2*c2, j1 = 2*c2 + 1;
            pfh[c2][0] = packbf(p[j0][0], p[j0][1]);
            pfh[c2][1] = packbf(p[j0][2], p[j0][3]);
            pfh[c2][2] = packbf(p[j1][0], p[j1][1]);
            pfh[c2][3] = packbf(p[j1][2], p[j1][3]);
            pfl[c2][0] = packbf(p[j0][0] - lo16f(pfh[c2][0]), p[j0][1] - hi16f(pfh[c2][0]));
            pfl[c2][1] = packbf(p[j0][2] - lo16f(pfh[c2][1]), p[j0][3] - hi16f(pfh[c2][1]));
            pfl[c2][2] = packbf(p[j1][0] - lo16f(pfh[c2][2]), p[j1][1] - hi16f(pfh[c2][2]));
            pfl[c2][3] = packbf(p[j1][2] - lo16f(pfh[c2][3]), p[j1][3] - hi16f(pfh[c2][3]));
        }

        #pragma unroll
        for (int c2 = 0; c2 < 4; c2++)
            #pragma unroll
            for (int j = 0; j < 8; j++) {
                uint bhv[2], blv[2];
                bhv[0] = *(uint*)&sVh[8*j + g][c2*16 + t*2];
                bhv[1] = *(uint*)&sVh[8*j + g][c2*16 + t*2 + 8];
                blv[0] = *(uint*)&sVl[8*j + g][c2*16 + t*2];
                blv[1] = *(uint*)&sVl[8*j + g][c2*16 + t*2 + 8];
                mma_bf16(o_[j], pfh[c2], bhv);
                mma_bf16(o_[j], pfh[c2], blv);
                mma_bf16(o_[j], pfl[c2], bhv);
            }
    }

    lrow0 += __shfl_xor_sync(0xffffffffu, lrow0, 1);
    lrow0 += __shfl_xor_sync(0xffffffffu, lrow0, 2);
    lrow1 += __shfl_xor_sync(0xffffffffu, lrow1, 1);
    lrow1 += __shfl_xor_sync(0xffffffffu, lrow1, 2);
    float inv0 = 1.0f / lrow0, inv1 = 1.0f / lrow1;

    int row0 = q0 + g, row1 = q0 + g + 8;
    size_t ob0 = ((size_t)b * T_LEN + row0) * D_MODEL + h * D_K;
    size_t ob1 = ((size_t)b * T_LEN + row1) * D_MODEL + h * D_K;
    #pragma unroll
    for (int j = 0; j < 8; j++) {
        int col = 8*j + t*2;
        float v00 = o_[j][0] * inv0, v01 = o_[j][1] * inv0;
        float v10 = o_[j][2] * inv1, v11 = o_[j][3] * inv1;
        __nv_bfloat16 h00, l00, h01, l01, h10, l10, h11, l11;
        bf16_split(v00, h00, l00); bf16_split(v01, h01, l01);
        bf16_split(v10, h10, l10); bf16_split(v11, h11, l11);
        *(__nv_bfloat162*)(oh_out + ob0 + col) = __nv_bfloat162(h00, h01);
        *(__nv_bfloat162*)(ol_out + ob0 + col) = __nv_bfloat162(l00, l01);
        *(__nv_bfloat162*)(oh_out + ob1 + col) = __nv_bfloat162(h10, h11);
        *(__nv_bfloat162*)(ol_out + ob1 + col) = __nv_bfloat162(l10, l11);
    }
}

// ============================================================
// Kernel 4: residual + LN(eps 1e-6) + outer residual
// ============================================================
__global__ __launch_bounds__(128) void ln2_kernel(
    const float* __restrict__ y,
    const float* __restrict__ h,
    const float* __restrict__ x,
    const float* __restrict__ g2,
    const float* __restrict__ b2,
    float* __restrict__ out)
{
    int r   = blockIdx.x;
    int tid = threadIdx.x;
    float4 yv = ((const float4*)(y + (size_t)r * D_MODEL))[tid];
    float4 hv = ((const float4*)(h + (size_t)r * D_MODEL))[tid];
    float4 tv;
    tv.x = yv.x + hv.x; tv.y = yv.y + hv.y;
    tv.z = yv.z + hv.z; tv.w = yv.w + hv.w;

    float sum = tv.x + tv.y + tv.z + tv.w;
    float sq  = tv.x*tv.x + tv.y*tv.y + tv.z*tv.z + tv.w*tv.w;
    #pragma unroll
    for (int off = 16; off; off >>= 1) {
        sum += __shfl_xor_sync(0xffffffffu, sum, off);
        sq  += __shfl_xor_sync(0xffffffffu, sq,  off);
    }
    __shared__ float s1[4], s2[4];
    if ((tid & 31) == 0) { s1[tid >> 5] = sum; s2[tid >> 5] = sq; }
    __syncthreads();
    sum = s1[0] + s1[1] + s1[2] + s1[3];
    sq  = s2[0] + s2[1] + s2[2] + s2[3];

    float mean = sum * (1.0f / D_MODEL);
    float var  = sq  * (1.0f / D_MODEL) - mean * mean;
    float rstd = rsqrtf(var + 1e-6f);

    float4 xv = ((const float4*)(x + (size_t)r * D_MODEL))[tid];
    const float* tp = (const float*)&tv;
    const float* xp = (const float*)&xv;
    int c0 = tid * 4;
    float4 ov; float* op = (float*)&ov;
    #pragma unroll
    for (int u = 0; u < 4; u++) {
        int c = c0 + u;
        op[u] = (tp[u] - mean) * rstd * g2[c] + b2[c] + xp[u];
    }
    ((float4*)(out + (size_t)r * D_MODEL))[tid] = ov;
}

// ============================================================
// launch
// ============================================================
extern "C" void kernel_launch(void* const* d_in, const int* in_sizes, int n_in,
                              void* d_out, int out_size)
{
    const float* x   = (const float*)d_in[0];
    const float* g1  = (const float*)d_in[1];
    const float* b1  = (const float*)d_in[2];
    const float* wq  = (const float*)d_in[3];
    const float* wk  = (const float*)d_in[4];
    const float* wv  = (const float*)d_in[5];
    const float* wfc = (const float*)d_in[6];
    const float* g2  = (const float*)d_in[7];
    const float* b2  = (const float*)d_in[8];
    float* out = (float*)d_out;

    float *ph, *py;
    __nv_bfloat16 *phh, *phl, *pqh, *pql, *pkh, *pkl, *pvh, *pvl, *poh, *pol, *pwh, *pwl;
    cudaGetSymbolAddress((void**)&ph,  g_h);
    cudaGetSymbolAddress((void**)&phh, g_hh);
    cudaGetSymbolAddress((void**)&phl, g_hl);
    cudaGetSymbolAddress((void**)&pqh, g_qh);
    cudaGetSymbolAddress((void**)&pql, g_ql);
    cudaGetSymbolAddress((void**)&pkh, g_kh);
    cudaGetSymbolAddress((void**)&pkl, g_kl);
    cudaGetSymbolAddress((void**)&pvh, g_vh);
    cudaGetSymbolAddress((void**)&pvl, g_vl);
    cudaGetSymbolAddress((void**)&poh, g_oh);
    cudaGetSymbolAddress((void**)&pol, g_ol);
    cudaGetSymbolAddress((void**)&py,  g_y);
    cudaGetSymbolAddress((void**)&pwh, g_wh);
    cudaGetSymbolAddress((void**)&pwl, g_wl);

    static bool attr_done = false;
    if (!attr_done) {
        cudaFuncSetAttribute(gemm_bf16<0>, cudaFuncAttributeMaxDynamicSharedMemorySize, GEMM_SMEM);
        cudaFuncSetAttribute(gemm_bf16<1>, cudaFuncAttributeMaxDynamicSharedMemorySize, GEMM_SMEM);
        cudaFuncSetAttribute(gemm_bf16<2>, cudaFuncAttributeMaxDynamicSharedMemorySize, GEMM_SMEM);
        attr_done = true;
    }

    const int WSZ = D_MODEL * D_MODEL;
    split_w_kernel<<<dim3(16, 16, 4), dim3(32, 8)>>>(wq, wk, wv, wfc, pwh, pwl);

    ln1_pe_kernel<<<NROWS, 128>>>(x, g1, b1, ph, phh, phl);

    dim3 gg(D_MODEL / BN, NROWS / BM);   // (8, 64)
    gemm_bf16<1><<<gg, 256, GEMM_SMEM>>>(phh, phl, pwh + 0 * WSZ, pwl + 0 * WSZ, nullptr, pqh, pql, 0.125f);
    gemm_bf16<1><<<gg, 256, GEMM_SMEM>>>(phh, phl, pwh + 1 * WSZ, pwl + 1 * WSZ, nullptr, pkh, pkl, 1.0f);
    gemm_bf16<2><<<gg, 256, GEMM_SMEM>>>(phh, phl, pwh + 2 * WSZ, pwl + 2 * WSZ, nullptr, pvh, pvl, 1.0f);

    attn_mma<<<dim3(T_LEN / 64, BATCH * N_HEADS), 128>>>(
        pqh, pql, pkh, pkl, pvh, pvl, poh, pol);

    gemm_bf16<0><<<gg, 256, GEMM_SMEM>>>(poh, pol, pwh + 3 * WSZ, pwl + 3 * WSZ, py, nullptr, nullptr, 1.0f);

    ln2_kernel<<<NROWS, 128>>>(py, ph, x, g2, b2, out);
}

// round 15
// speedup vs baseline: 3.8254x; 1.0629x over previous
#include <cuda_runtime.h>
#include <cuda_bf16.h>
#include <math.h>

#define D_MODEL 512
#define T_LEN   2048
#define BATCH   4
#define NROWS   (BATCH * T_LEN)   // 8192
#define N_HEADS 8
#define D_K     64

typedef unsigned int uint;

// -------- scratch --------
__device__ float          g_h  [NROWS * D_MODEL];  // LN1(x)+PE fp32 (residual1)
__device__ __nv_bfloat16  g_hh [NROWS * D_MODEL];
__device__ __nv_bfloat16  g_hl [NROWS * D_MODEL];
__device__ __nv_bfloat16  g_qh [NROWS * D_MODEL];  // [B,H,T,64]  (pre-scaled by 0.125)
__device__ __nv_bfloat16  g_ql [NROWS * D_MODEL];
__device__ __nv_bfloat16  g_kh [NROWS * D_MODEL];  // [B,H,T,64]
__device__ __nv_bfloat16  g_kl [NROWS * D_MODEL];
__device__ __nv_bfloat16  g_vh [NROWS * D_MODEL];  // [B,H,T,64]  (same layout as K now)
__device__ __nv_bfloat16  g_vl [NROWS * D_MODEL];
__device__ __nv_bfloat16  g_oh [NROWS * D_MODEL];  // attn out [B,T,512]
__device__ __nv_bfloat16  g_ol [NROWS * D_MODEL];
__device__ float          g_y  [NROWS * D_MODEL];
__device__ __nv_bfloat16  g_wh [4 * D_MODEL * D_MODEL];  // W^T [n][k], hi
__device__ __nv_bfloat16  g_wl [4 * D_MODEL * D_MODEL];  // W^T [n][k], lo

__device__ __forceinline__ void bf16_split(float x, __nv_bfloat16& h, __nv_bfloat16& l) {
    h = __float2bfloat16(x);
    l = __float2bfloat16(x - __bfloat162float(h));
}
__device__ __forceinline__ uint packbf(float lo, float hi) {
    uint r;
    asm("cvt.rn.bf16x2.f32 %0, %1, %2;" : "=r"(r) : "f"(hi), "f"(lo));
    return r;
}
__device__ __forceinline__ float lo16f(uint u) { return __uint_as_float(u << 16); }
__device__ __forceinline__ float hi16f(uint u) { return __uint_as_float(u & 0xffff0000u); }

__device__ __forceinline__ void mma_bf16(float* d, const uint* a, const uint* b) {
    asm volatile(
        "mma.sync.aligned.m16n8k16.row.col.f32.bf16.bf16.f32 "
        "{%0,%1,%2,%3},{%4,%5,%6,%7},{%8,%9},{%0,%1,%2,%3};\n"
        : "+f"(d[0]), "+f"(d[1]), "+f"(d[2]), "+f"(d[3])
        : "r"(a[0]), "r"(a[1]), "r"(a[2]), "r"(a[3]), "r"(b[0]), "r"(b[1]));
}
__device__ __forceinline__ void ldsm4(uint* r, uint addr) {
    asm volatile("ldmatrix.sync.aligned.m8n8.x4.shared.b16 {%0,%1,%2,%3}, [%4];"
        : "=r"(r[0]), "=r"(r[1]), "=r"(r[2]), "=r"(r[3]) : "r"(addr));
}
__device__ __forceinline__ void ldsm4t(uint* r, uint addr) {
    asm volatile("ldmatrix.sync.aligned.m8n8.x4.trans.shared.b16 {%0,%1,%2,%3}, [%4];"
        : "=r"(r[0]), "=r"(r[1]), "=r"(r[2]), "=r"(r[3]) : "r"(addr));
}
__device__ __forceinline__ void cp_async16(uint dst, const void* src) {
    asm volatile("cp.async.cg.shared.global [%0], [%1], 16;" :: "r"(dst), "l"(src));
}
__device__ __forceinline__ void cp_commit() { asm volatile("cp.async.commit_group;"); }
template<int N> __device__ __forceinline__ void cp_wait() {
    asm volatile("cp.async.wait_group %0;" :: "n"(N));
}

// ============================================================
// Weight split + transpose: w[k][n] fp32 -> wh/wl[n][k] bf16
// ============================================================
__global__ __launch_bounds__(256) void split_w_kernel(
    const float* __restrict__ w0, const float* __restrict__ w1,
    const float* __restrict__ w2, const float* __restrict__ w3,
    __nv_bfloat16* __restrict__ wh, __nv_bfloat16* __restrict__ wl)
{
    const int WSZ = D_MODEL * D_MODEL;
    __shared__ float tile[32][33];
    int wsel = blockIdx.z;
    const float* w = (wsel == 0) ? w0 : (wsel == 1) ? w1 : (wsel == 2) ? w2 : w3;
    int n0 = blockIdx.x * 32, k0 = blockIdx.y * 32;
    int tx = threadIdx.x, ty = threadIdx.y;
    #pragma unroll
    for (int j = 0; j < 32; j += 8)
        tile[ty + j][tx] = w[(size_t)(k0 + ty + j) * D_MODEL + n0 + tx];
    __syncthreads();
    #pragma unroll
    for (int j = 0; j < 32; j += 8) {
        float v = tile[tx][ty + j];
        __nv_bfloat16 h, l;
        bf16_split(v, h, l);
        size_t o = (size_t)wsel * WSZ + (size_t)(n0 + ty + j) * D_MODEL + k0 + tx;
        wh[o] = h; wl[o] = l;
    }
}

// ============================================================
// Kernel 1: LN(eps 1e-5) + sinusoidal PE -> fp32 + bf16 split
// ============================================================
__global__ __launch_bounds__(128) void ln1_pe_kernel(
    const float* __restrict__ x,
    const float* __restrict__ gam,
    const float* __restrict__ bet,
    float* __restrict__ h_out,
    __nv_bfloat16* __restrict__ hh_out,
    __nv_bfloat16* __restrict__ hl_out)
{
    int r   = blockIdx.x;
    int tid = threadIdx.x;
    const float4 xv = ((const float4*)(x + (size_t)r * D_MODEL))[tid];

    float sum = xv.x + xv.y + xv.z + xv.w;
    float sq  = xv.x*xv.x + xv.y*xv.y + xv.z*xv.z + xv.w*xv.w;
    #pragma unroll
    for (int off = 16; off; off >>= 1) {
        sum += __shfl_xor_sync(0xffffffffu, sum, off);
        sq  += __shfl_xor_sync(0xffffffffu, sq,  off);
    }
    __shared__ float s1[4], s2[4];
    if ((tid & 31) == 0) { s1[tid >> 5] = sum; s2[tid >> 5] = sq; }
    __syncthreads();
    sum = s1[0] + s1[1] + s1[2] + s1[3];
    sq  = s2[0] + s2[1] + s2[2] + s2[3];

    float mean = sum * (1.0f / D_MODEL);
    float var  = sq  * (1.0f / D_MODEL) - mean * mean;
    float rstd = rsqrtf(var + 1e-5f);

    int t  = r & (T_LEN - 1);
    int c0 = tid * 4;
    const float* xp = (const float*)&xv;
    float4 hv; float* hp = (float*)&hv;
    __nv_bfloat16 hb[4], lb[4];
    #pragma unroll
    for (int u = 0; u < 4; u++) {
        int c = c0 + u;
        float div = expf((float)(c & ~1) * (-9.2103403719761836f / 512.0f));
        float ang = (float)t * div;
        float pe  = (c & 1) ? cosf(ang) : sinf(ang);
        hp[u] = (xp[u] - mean) * rstd * gam[c] + bet[c] + pe;
        bf16_split(hp[u], hb[u], lb[u]);
    }
    ((float4*)(h_out + (size_t)r * D_MODEL))[tid] = hv;
    size_t base = (size_t)r * D_MODEL + c0;
    *(__nv_bfloat162*)(hh_out + base    ) = __nv_bfloat162(hb[0], hb[1]);
    *(__nv_bfloat162*)(hh_out + base + 2) = __nv_bfloat162(hb[2], hb[3]);
    *(__nv_bfloat162*)(hl_out + base    ) = __nv_bfloat162(lb[0], lb[1]);
    *(__nv_bfloat162*)(hl_out + base + 2) = __nv_bfloat162(lb[2], lb[3]);
}

// ============================================================
// Kernel 2: bf16 MMA GEMM, 3-stage cp.async pipeline + ldmatrix.
// A [M][K] row-major, W^T [N][K] row-major. 2-term compensation.
// BM=128 BN=64 BK=32, 256 threads, 2 CTAs/SM.
// MODE 1: fused QKV — blockIdx.z selects weight/output/scale;
//         bf16 split out [B,H,T,64] (Q scaled by 0.125).
// MODE 0: fp32 row-major out (wfc).
// ============================================================
#define BM 128
#define BN 64
#define BK 32
#define AST 40                    // row stride elems (80B = 5x16B)
#define A_STAGE (BM * AST)        // 5120 elems
#define W_STAGE (BN * AST)        // 2560 elems
#define STAGES 3
#define GEMM_SMEM (STAGES * (A_STAGE + W_STAGE) * 2 * 2)   // 92160 bytes

template<int MODE>
__global__ __launch_bounds__(256, 2) void gemm_bf16(
    const __nv_bfloat16* __restrict__ Ah, const __nv_bfloat16* __restrict__ Al,
    const __nv_bfloat16* __restrict__ Wh_base, const __nv_bfloat16* __restrict__ Wl_base,
    float* __restrict__ C,
    __nv_bfloat16* __restrict__ Qh, __nv_bfloat16* __restrict__ Ql,
    __nv_bfloat16* __restrict__ Kh, __nv_bfloat16* __restrict__ Kl,
    __nv_bfloat16* __restrict__ Vh, __nv_bfloat16* __restrict__ Vl)
{
    const int K = 512, N = 512;
    const int WSZ = D_MODEL * D_MODEL;
    int z = (MODE == 1) ? blockIdx.z : 0;
    const __nv_bfloat16* Wh = Wh_base + (size_t)z * WSZ;
    const __nv_bfloat16* Wl = Wl_base + (size_t)z * WSZ;

    extern __shared__ __nv_bfloat16 smem[];
    __nv_bfloat16* pAh = smem;                          // [STAGES][BM][AST]
    __nv_bfloat16* pAl = pAh + STAGES * A_STAGE;
    __nv_bfloat16* pWh = pAl + STAGES * A_STAGE;        // [STAGES][BN][AST]
    __nv_bfloat16* pWl = pWh + STAGES * W_STAGE;

    uint bAh = (uint)__cvta_generic_to_shared(pAh);
    uint bAl = (uint)__cvta_generic_to_shared(pAl);
    uint bWh = (uint)__cvta_generic_to_shared(pWh);
    uint bWl = (uint)__cvta_generic_to_shared(pWl);

    int tid  = threadIdx.x;
    int m0   = blockIdx.y * BM;
    int n0   = blockIdx.x * BN;
    int warp = tid >> 5, lane = tid & 31;
    int wm   = (warp >> 1) * 32;
    int wn   = (warp & 1) * 32;
    int g    = lane >> 2, t = lane & 3;

    // cp.async source/dst indices
    int ar = tid >> 2;              // A row (first half), +64 for second
    int ac = (tid & 3) << 3;        // col in elems {0,8,16,24}
    const size_t gAoff0 = (size_t)(m0 + ar) * K + ac;
    const size_t gAoff1 = (size_t)(m0 + ar + 64) * K + ac;
    const size_t gWoff  = (size_t)(n0 + ar) * K + ac;   // ar<64 covers W rows
    const uint sAoff0 = (ar * AST + ac) * 2;
    const uint sAoff1 = ((ar + 64) * AST + ac) * 2;
    const uint sWoff  = (ar * AST + ac) * 2;

    // ldmatrix row offsets (elems, before *2 bytes)
    const int aRow = (wm + (lane & 15)) * AST + ((lane >> 4) << 3);
    const int bRow = (wn + (lane & 7) + ((lane >> 4) << 3)) * AST + (((lane >> 3) & 1) << 3);

    float acc[2][4][4];
    #pragma unroll
    for (int i = 0; i < 2; i++)
        #pragma unroll
        for (int j = 0; j < 4; j++)
            #pragma unroll
            for (int e = 0; e < 4; e++) acc[i][j][e] = 0.0f;

    auto issue = [&](int k0, int st) {
        uint sa = st * A_STAGE * 2, sw = st * W_STAGE * 2;
        cp_async16(bAh + sa + sAoff0, Ah + gAoff0 + k0);
        cp_async16(bAh + sa + sAoff1, Ah + gAoff1 + k0);
        cp_async16(bAl + sa + sAoff0, Al + gAoff0 + k0);
        cp_async16(bAl + sa + sAoff1, Al + gAoff1 + k0);
        cp_async16(bWh + sw + sWoff, Wh + gWoff + k0);
        cp_async16(bWl + sw + sWoff, Wl + gWoff + k0);
    };

    issue(0, 0); cp_commit();
    issue(BK, 1); cp_commit();
    const int NT = K / BK;  // 16
    for (int it = 0; it < NT; it++) {
        int st = it % STAGES;
        if (it + 2 < NT) {
            cp_wait<1>(); __syncthreads();
            issue((it + 2) * BK, (it + 2) % STAGES); cp_commit();
        } else {
            cp_wait<0>(); __syncthreads();
        }

        uint sa = st * A_STAGE * 2, sw = st * W_STAGE * 2;
        #pragma unroll
        for (int ks = 0; ks < BK; ks += 16) {
            uint a_h[2][4], a_l[2][4], b_h[2][4], b_l[2][4];
            #pragma unroll
            for (int mt = 0; mt < 2; mt++) {
                uint off = sa + (aRow + mt * 16 * AST + ks) * 2;
                ldsm4(a_h[mt], bAh + off);
                ldsm4(a_l[mt], bAl + off);
            }
            #pragma unroll
            for (int nt2 = 0; nt2 < 2; nt2++) {
                uint off = sw + (bRow + nt2 * 16 * AST + ks) * 2;
                ldsm4(b_h[nt2], bWh + off);
                ldsm4(b_l[nt2], bWl + off);
            }
            #pragma unroll
            for (int mt = 0; mt < 2; mt++)
                #pragma unroll
                for (int nt = 0; nt < 4; nt++) {
                    const uint* bh = &b_h[nt >> 1][(nt & 1) * 2];
                    const uint* bl = &b_l[nt >> 1][(nt & 1) * 2];
                    mma_bf16(acc[mt][nt], a_h[mt], bh);
                    mma_bf16(acc[mt][nt], a_h[mt], bl);
                    mma_bf16(acc[mt][nt], a_l[mt], bh);
                }
        }
        __syncthreads();
    }

    // ---- epilogue ----
    float ascale = (MODE == 1 && z == 0) ? 0.125f : 1.0f;
    __nv_bfloat16* Ch = (z == 0) ? Qh : (z == 1) ? Kh : Vh;
    __nv_bfloat16* Cl = (z == 0) ? Ql : (z == 1) ? Kl : Vl;

    #pragma unroll
    for (int mt = 0; mt < 2; mt++)
        #pragma unroll
        for (int nt = 0; nt < 4; nt++) {
            float* a = acc[mt][nt];
            int m = m0 + wm + mt * 16 + g;
            int n = n0 + wn + nt * 8 + t * 2;
            if (MODE == 0) {
                *(float2*)(C + (size_t)m * N + n)       = make_float2(a[0], a[1]);
                *(float2*)(C + (size_t)(m + 8) * N + n) = make_float2(a[2], a[3]);
            } else {
                #pragma unroll
                for (int half = 0; half < 2; half++) {
                    int mm = m + half * 8;
                    int bb = mm >> 11, tt = mm & (T_LEN - 1);
                    int hh = n >> 6,  dd = n & 63;
                    size_t addr = (((size_t)bb * N_HEADS + hh) * T_LEN + tt) * D_K + dd;
                    __nv_bfloat16 h0, l0, h1, l1;
                    bf16_split(a[half*2+0] * ascale, h0, l0);
                    bf16_split(a[half*2+1] * ascale, h1, l1);
                    *(__nv_bfloat162*)(Ch + addr) = __nv_bfloat162(h0, h1);
                    *(__nv_bfloat162*)(Cl + addr) = __nv_bfloat162(l0, l1);
                }
            }
        }
}

// ============================================================
// Kernel 3: bf16 MMA causal flash attention, ldmatrix fragments.
// grid (32 q-blocks reversed, 32 bh), 128 threads = 4 warps, m16/warp.
// K and V both [B,H,T,64]; V^T fragments via ldmatrix.trans.
// ============================================================
__global__ __launch_bounds__(128) void attn_mma(
    const __nv_bfloat16* __restrict__ qh_in, const __nv_bfloat16* __restrict__ ql_in,
    const __nv_bfloat16* __restrict__ kh_in, const __nv_bfloat16* __restrict__ kl_in,
    const __nv_bfloat16* __restrict__ vh_in, const __nv_bfloat16* __restrict__ vl_in,
    __nv_bfloat16* __restrict__ oh_out, __nv_bfloat16* __restrict__ ol_out)
{
    int qb   = (int)gridDim.x - 1 - (int)blockIdx.x;   // big blocks first
    int bh   = blockIdx.y;
    int b    = bh >> 3, h = bh & 7;
    int warp = threadIdx.x >> 5, lane = threadIdx.x & 31;
    int g    = lane >> 2, t = lane & 3;
    int q0   = qb * 64 + warp * 16;

    __shared__ __nv_bfloat16 sKh[64][72], sKl[64][72];   // [kv][d]
    __shared__ __nv_bfloat16 sVh[64][72], sVl[64][72];   // [kv][d]

    uint bKh = (uint)__cvta_generic_to_shared(&sKh[0][0]);
    uint bKl = (uint)__cvta_generic_to_shared(&sKl[0][0]);
    uint bVh = (uint)__cvta_generic_to_shared(&sVh[0][0]);
    uint bVl = (uint)__cvta_generic_to_shared(&sVl[0][0]);
    // common ldmatrix lane offset: row (lane&15), col-half (lane>>4)*8
    const uint lrow = ((lane & 15) * 72 + ((lane >> 4) << 3)) * 2;

    uint qfh[4][4], qfl[4][4];
    {
        const size_t qb0 = (size_t)bh * T_LEN * D_K;
        #pragma unroll
        for (int c = 0; c < 4; c++)
            #pragma unroll
            for (int p = 0; p < 4; p++) {
                int row = q0 + g + (p & 1) * 8;
                int col = c * 16 + t * 2 + (p >> 1) * 8;
                qfh[c][p] = *(const uint*)(qh_in + qb0 + (size_t)row * D_K + col);
                qfl[c][p] = *(const uint*)(ql_in + qb0 + (size_t)row * D_K + col);
            }
    }

    float o_[8][4];
    #pragma unroll
    for (int j = 0; j < 8; j++)
        #pragma unroll
        for (int e = 0; e < 4; e++) o_[j][e] = 0.0f;
    float mrow0 = -1e30f, mrow1 = -1e30f, lrow0 = 0.0f, lrow1 = 0.0f;

    int tr = threadIdx.x >> 1;
    int tc = (threadIdx.x & 1) * 32;

    int ntiles = qb + 1;
    for (int kt = 0; kt < ntiles; kt++) {
        int kv0 = kt * 64;
        __syncthreads();
        {
            const size_t kb = ((size_t)bh * T_LEN + kv0 + tr) * D_K + tc;
            #pragma unroll
            for (int i = 0; i < 4; i++) {
                *(uint4*)&sKh[tr][tc + i * 8] = *(const uint4*)(kh_in + kb + i * 8);
                *(uint4*)&sKl[tr][tc + i * 8] = *(const uint4*)(kl_in + kb + i * 8);
                *(uint4*)&sVh[tr][tc + i * 8] = *(const uint4*)(vh_in + kb + i * 8);
                *(uint4*)&sVl[tr][tc + i * 8] = *(const uint4*)(vl_in + kb + i * 8);
            }
        }
        __syncthreads();

        // ---- S = Q K^T  (B-fragments via ldmatrix, 16kv x 16d tiles) ----
        float s[8][4];
        #pragma unroll
        for (int j = 0; j < 8; j++)
            #pragma unroll
            for (int e = 0; e < 4; e++) s[j][e] = 0.0f;

        #pragma unroll
        for (int c = 0; c < 4; c++)
            #pragma unroll
            for (int sv = 0; sv < 4; sv++) {
                uint kh4[4], kl4[4];
                uint off = (uint)(sv * 16 * 72 + c * 16) * 2 + lrow;
                ldsm4(kh4, bKh + off);
                ldsm4(kl4, bKl + off);
                uint b0h[2] = {kh4[0], kh4[2]}, b1h[2] = {kh4[1], kh4[3]};
                uint b0l[2] = {kl4[0], kl4[2]}, b1l[2] = {kl4[1], kl4[3]};
                mma_bf16(s[sv*2],   qfh[c], b0h);
                mma_bf16(s[sv*2],   qfh[c], b0l);
                mma_bf16(s[sv*2],   qfl[c], b0h);
                mma_bf16(s[sv*2+1], qfh[c], b1h);
                mma_bf16(s[sv*2+1], qfh[c], b1l);
                mma_bf16(s[sv*2+1], qfl[c], b1h);
            }

        // ---- causal mask on diagonal tile ----
        if (kt == qb) {
            #pragma unroll
            for (int j = 0; j < 8; j++)
                #pragma unroll
                for (int e = 0; e < 4; e++) {
                    int col = 8*j + t*2 + (e & 1);
                    int row = warp*16 + g + (e >> 1) * 8;
                    if (col > row) s[j][e] = -1e30f;
                }
        }

        // ---- online softmax ----
        float mx0 = -1e30f, mx1 = -1e30f;
        #pragma unroll
        for (int j = 0; j < 8; j++) {
            mx0 = fmaxf(mx0, fmaxf(s[j][0], s[j][1]));
            mx1 = fmaxf(mx1, fmaxf(s[j][2], s[j][3]));
        }
        mx0 = fmaxf(mx0, __shfl_xor_sync(0xffffffffu, mx0, 1));
        mx0 = fmaxf(mx0, __shfl_xor_sync(0xffffffffu, mx0, 2));
        mx1 = fmaxf(mx1, __shfl_xor_sync(0xffffffffu, mx1, 1));
        mx1 = fmaxf(mx1, __shfl_xor_sync(0xffffffffu, mx1, 2));

        float nm0 = fmaxf(mrow0, mx0), nm1 = fmaxf(mrow1, mx1);
        float sc0 = __expf(mrow0 - nm0), sc1 = __expf(mrow1 - nm1);
        mrow0 = nm0; mrow1 = nm1;
        lrow0 *= sc0; lrow1 *= sc1;
        #pragma unroll
        for (int j = 0; j < 8; j++) {
            o_[j][0] *= sc0; o_[j][1] *= sc0;
            o_[j][2] *= sc1; o_[j][3] *= sc1;
        }

        float p[8][4];
        #pragma unroll
        for (int j = 0; j < 8; j++) {
            p[j][0] = __expf(s[j][0] - nm0);
            p[j][1] = __expf(s[j][1] - nm0);
            p[j][2] = __expf(s[j][2] - nm1);
            p[j][3] = __expf(s[j][3] - nm1);
            lrow0 += p[j][0] + p[j][1];
            lrow1 += p[j][2] + p[j][3];
        }

        // ---- pack P into A-fragments (register-only) ----
        uint pfh[4][4], pfl[4][4];
        #pragma unroll
        for (int c2 = 0; c2 < 4; c2++) {
            int j0 = 2*c2, j1 = 2*c2 + 1;
            pfh[c2][0] = packbf(p[j0][0], p[j0][1]);
            pfh[c2][1] = packbf(p[j0][2], p[j0][3]);
            pfh[c2][2] = packbf(p[j1][0], p[j1][1]);
            pfh[c2][3] = packbf(p[j1][2], p[j1][3]);
            pfl[c2][0] = packbf(p[j0][0] - lo16f(pfh[c2][0]), p[j0][1] - hi16f(pfh[c2][0]));
            pfl[c2][1] = packbf(p[j0][2] - lo16f(pfh[c2][1]), p[j0][3] - hi16f(pfh[c2][1]));
            pfl[c2][2] = packbf(p[j1][0] - lo16f(pfh[c2][2]), p[j1][1] - hi16f(pfh[c2][2]));
            pfl[c2][3] = packbf(p[j1][2] - lo16f(pfh[c2][3]), p[j1][3] - hi16f(pfh[c2][3]));
        }

        // ---- O += P V  (V^T B-fragments via ldmatrix.trans) ----
        #pragma unroll
        for (int c2 = 0; c2 < 4; c2++)
            #pragma unroll
            for (int dsub = 0; dsub < 4; dsub++) {
                uint vh4[4], vl4[4];
                uint off = (uint)(c2 * 16 * 72 + dsub * 16) * 2 + lrow;
                ldsm4t(vh4, bVh + off);
                ldsm4t(vl4, bVl + off);
                mma_bf16(o_[dsub*2],   pfh[c2], &vh4[0]);
                mma_bf16(o_[dsub*2],   pfh[c2], &vl4[0]);
                mma_bf16(o_[dsub*2],   pfl[c2], &vh4[0]);
                mma_bf16(o_[dsub*2+1], pfh[c2], &vh4[2]);
                mma_bf16(o_[dsub*2+1], pfh[c2], &vl4[2]);
                mma_bf16(o_[dsub*2+1], pfl[c2], &vh4[2]);
            }
    }

    // ---- finalize ----
    lrow0 += __shfl_xor_sync(0xffffffffu, lrow0, 1);
    lrow0 += __shfl_xor_sync(0xffffffffu, lrow0, 2);
    lrow1 += __shfl_xor_sync(0xffffffffu, lrow1, 1);
    lrow1 += __shfl_xor_sync(0xffffffffu, lrow1, 2);
    float inv0 = 1.0f / lrow0, inv1 = 1.0f / lrow1;

    int row0 = q0 + g, row1 = q0 + g + 8;
    size_t ob0 = ((size_t)b * T_LEN + row0) * D_MODEL + h * D_K;
    size_t ob1 = ((size_t)b * T_LEN + row1) * D_MODEL + h * D_K;
    #pragma unroll
    for (int j = 0; j < 8; j++) {
        int col = 8*j + t*2;
        float v00 = o_[j][0] * inv0, v01 = o_[j][1] * inv0;
        float v10 = o_[j][2] * inv1, v11 = o_[j][3] * inv1;
        __nv_bfloat16 h00, l00, h01, l01, h10, l10, h11, l11;
        bf16_split(v00, h00, l00); bf16_split(v01, h01, l01);
        bf16_split(v10, h10, l10); bf16_split(v11, h11, l11);
        *(__nv_bfloat162*)(oh_out + ob0 + col) = __nv_bfloat162(h00, h01);
        *(__nv_bfloat162*)(ol_out + ob0 + col) = __nv_bfloat162(l00, l01);
        *(__nv_bfloat162*)(oh_out + ob1 + col) = __nv_bfloat162(h10, h11);
        *(__nv_bfloat162*)(ol_out + ob1 + col) = __nv_bfloat162(l10, l11);
    }
}

// ============================================================
// Kernel 4: residual + LN(eps 1e-6) + outer residual
// ============================================================
__global__ __launch_bounds__(128) void ln2_kernel(
    const float* __restrict__ y,
    const float* __restrict__ h,
    const float* __restrict__ x,
    const float* __restrict__ g2,
    const float* __restrict__ b2,
    float* __restrict__ out)
{
    int r   = blockIdx.x;
    int tid = threadIdx.x;
    float4 yv = ((const float4*)(y + (size_t)r * D_MODEL))[tid];
    float4 hv = ((const float4*)(h + (size_t)r * D_MODEL))[tid];
    float4 tv;
    tv.x = yv.x + hv.x; tv.y = yv.y + hv.y;
    tv.z = yv.z + hv.z; tv.w = yv.w + hv.w;

    float sum = tv.x + tv.y + tv.z + tv.w;
    float sq  = tv.x*tv.x + tv.y*tv.y + tv.z*tv.z + tv.w*tv.w;
    #pragma unroll
    for (int off = 16; off; off >>= 1) {
        sum += __shfl_xor_sync(0xffffffffu, sum, off);
        sq  += __shfl_xor_sync(0xffffffffu, sq,  off);
    }
    __shared__ float s1[4], s2[4];
    if ((tid & 31) == 0) { s1[tid >> 5] = sum; s2[tid >> 5] = sq; }
    __syncthreads();
    sum = s1[0] + s1[1] + s1[2] + s1[3];
    sq  = s2[0] + s2[1] + s2[2] + s2[3];

    float mean = sum * (1.0f / D_MODEL);
    float var  = sq  * (1.0f / D_MODEL) - mean * mean;
    float rstd = rsqrtf(var + 1e-6f);

    float4 xv = ((const float4*)(x + (size_t)r * D_MODEL))[tid];
    const float* tp = (const float*)&tv;
    const float* xp = (const float*)&xv;
    int c0 = tid * 4;
    float4 ov; float* op = (float*)&ov;
    #pragma unroll
    for (int u = 0; u < 4; u++) {
        int c = c0 + u;
        op[u] = (tp[u] - mean) * rstd * g2[c] + b2[c] + xp[u];
    }
    ((float4*)(out + (size_t)r * D_MODEL))[tid] = ov;
}

// ============================================================
// launch
// ============================================================
extern "C" void kernel_launch(void* const* d_in, const int* in_sizes, int n_in,
                              void* d_out, int out_size)
{
    const float* x   = (const float*)d_in[0];
    const float* g1  = (const float*)d_in[1];
    const float* b1  = (const float*)d_in[2];
    const float* wq  = (const float*)d_in[3];
    const float* wk  = (const float*)d_in[4];
    const float* wv  = (const float*)d_in[5];
    const float* wfc = (const float*)d_in[6];
    const float* g2  = (const float*)d_in[7];
    const float* b2  = (const float*)d_in[8];
    float* out = (float*)d_out;

    float *ph, *py;
    __nv_bfloat16 *phh, *phl, *pqh, *pql, *pkh, *pkl, *pvh, *pvl, *poh, *pol, *pwh, *pwl;
    cudaGetSymbolAddress((void**)&ph,  g_h);
    cudaGetSymbolAddress((void**)&phh, g_hh);
    cudaGetSymbolAddress((void**)&phl, g_hl);
    cudaGetSymbolAddress((void**)&pqh, g_qh);
    cudaGetSymbolAddress((void**)&pql, g_ql);
    cudaGetSymbolAddress((void**)&pkh, g_kh);
    cudaGetSymbolAddress((void**)&pkl, g_kl);
    cudaGetSymbolAddress((void**)&pvh, g_vh);
    cudaGetSymbolAddress((void**)&pvl, g_vl);
    cudaGetSymbolAddress((void**)&poh, g_oh);
    cudaGetSymbolAddress((void**)&pol, g_ol);
    cudaGetSymbolAddress((void**)&py,  g_y);
    cudaGetSymbolAddress((void**)&pwh, g_wh);
    cudaGetSymbolAddress((void**)&pwl, g_wl);

    static bool attr_done = false;
    if (!attr_done) {
        cudaFuncSetAttribute(gemm_bf16<0>, cudaFuncAttributeMaxDynamicSharedMemorySize, GEMM_SMEM);
        cudaFuncSetAttribute(gemm_bf16<1>, cudaFuncAttributeMaxDynamicSharedMemorySize, GEMM_SMEM);
        attr_done = true;
    }

    const int WSZ = D_MODEL * D_MODEL;
    split_w_kernel<<<dim3(16, 16, 4), dim3(32, 8)>>>(wq, wk, wv, wfc, pwh, pwl);

    ln1_pe_kernel<<<NROWS, 128>>>(x, g1, b1, ph, phh, phl);

    // fused QKV: z = 0(Q, x0.125), 1(K), 2(V) — all [B,H,T,64] split outputs
    gemm_bf16<1><<<dim3(D_MODEL / BN, NROWS / BM, 3), 256, GEMM_SMEM>>>(
        phh, phl, pwh, pwl, nullptr, pqh, pql, pkh, pkl, pvh, pvl);

    attn_mma<<<dim3(T_LEN / 64, BATCH * N_HEADS), 128>>>(
        pqh, pql, pkh, pkl, pvh, pvl, poh, pol);

    gemm_bf16<0><<<dim3(D_MODEL / BN, NROWS / BM, 1), 256, GEMM_SMEM>>>(
        poh, pol, pwh + 3 * WSZ, pwl + 3 * WSZ, py,
        py == nullptr ? nullptr : nullptr, nullptr, nullptr, nullptr, nullptr, nullptr);

    ln2_kernel<<<NROWS, 128>>>(py, ph, x, g2, b2, out);
}

// round 17
// speedup vs baseline: 4.0230x; 1.0517x over previous
#include <cuda_runtime.h>
#include <cuda_bf16.h>
#include <math.h>

#define D_MODEL 512
#define T_LEN   2048
#define BATCH   4
#define NROWS   (BATCH * T_LEN)   // 8192
#define N_HEADS 8
#define D_K     64

typedef unsigned int uint;

// -------- scratch --------
__device__ float          g_h  [NROWS * D_MODEL];  // LN1(x)+PE fp32 (residual1)
__device__ __nv_bfloat16  g_hh [NROWS * D_MODEL];
__device__ __nv_bfloat16  g_hl [NROWS * D_MODEL];
__device__ __nv_bfloat16  g_qh [NROWS * D_MODEL];  // [B,H,T,64]  (pre-scaled by 0.125)
__device__ __nv_bfloat16  g_ql [NROWS * D_MODEL];
__device__ __nv_bfloat16  g_kh [NROWS * D_MODEL];  // [B,H,T,64]
__device__ __nv_bfloat16  g_kl [NROWS * D_MODEL];
__device__ __nv_bfloat16  g_vh [NROWS * D_MODEL];  // [B,H,T,64]
__device__ __nv_bfloat16  g_vl [NROWS * D_MODEL];
__device__ __nv_bfloat16  g_oh [NROWS * D_MODEL];  // attn out [B,T,512]
__device__ __nv_bfloat16  g_ol [NROWS * D_MODEL];
__device__ float          g_y  [NROWS * D_MODEL];
__device__ __nv_bfloat16  g_wh [4 * D_MODEL * D_MODEL];  // W^T [n][k], hi
__device__ __nv_bfloat16  g_wl [4 * D_MODEL * D_MODEL];  // W^T [n][k], lo

__device__ __forceinline__ void bf16_split(float x, __nv_bfloat16& h, __nv_bfloat16& l) {
    h = __float2bfloat16(x);
    l = __float2bfloat16(x - __bfloat162float(h));
}
__device__ __forceinline__ uint packbf(float lo, float hi) {
    uint r;
    asm("cvt.rn.bf16x2.f32 %0, %1, %2;" : "=r"(r) : "f"(hi), "f"(lo));
    return r;
}
__device__ __forceinline__ float lo16f(uint u) { return __uint_as_float(u << 16); }
__device__ __forceinline__ float hi16f(uint u) { return __uint_as_float(u & 0xffff0000u); }

__device__ __forceinline__ void mma_bf16(float* d, const uint* a, const uint* b) {
    asm volatile(
        "mma.sync.aligned.m16n8k16.row.col.f32.bf16.bf16.f32 "
        "{%0,%1,%2,%3},{%4,%5,%6,%7},{%8,%9},{%0,%1,%2,%3};\n"
        : "+f"(d[0]), "+f"(d[1]), "+f"(d[2]), "+f"(d[3])
        : "r"(a[0]), "r"(a[1]), "r"(a[2]), "r"(a[3]), "r"(b[0]), "r"(b[1]));
}
__device__ __forceinline__ void ldsm4(uint* r, uint addr) {
    asm volatile("ldmatrix.sync.aligned.m8n8.x4.shared.b16 {%0,%1,%2,%3}, [%4];"
        : "=r"(r[0]), "=r"(r[1]), "=r"(r[2]), "=r"(r[3]) : "r"(addr));
}
__device__ __forceinline__ void ldsm4t(uint* r, uint addr) {
    asm volatile("ldmatrix.sync.aligned.m8n8.x4.trans.shared.b16 {%0,%1,%2,%3}, [%4];"
        : "=r"(r[0]), "=r"(r[1]), "=r"(r[2]), "=r"(r[3]) : "r"(addr));
}
__device__ __forceinline__ void cp_async16(uint dst, const void* src) {
    asm volatile("cp.async.cg.shared.global [%0], [%1], 16;" :: "r"(dst), "l"(src));
}
__device__ __forceinline__ void cp_commit() { asm volatile("cp.async.commit_group;"); }
template<int N> __device__ __forceinline__ void cp_wait() {
    asm volatile("cp.async.wait_group %0;" :: "n"(N));
}

// ============================================================
// Weight split + transpose: w[k][n] fp32 -> wh/wl[n][k] bf16
// ============================================================
__global__ __launch_bounds__(256) void split_w_kernel(
    const float* __restrict__ w0, const float* __restrict__ w1,
    const float* __restrict__ w2, const float* __restrict__ w3,
    __nv_bfloat16* __restrict__ wh, __nv_bfloat16* __restrict__ wl)
{
    const int WSZ = D_MODEL * D_MODEL;
    __shared__ float tile[32][33];
    int wsel = blockIdx.z;
    const float* w = (wsel == 0) ? w0 : (wsel == 1) ? w1 : (wsel == 2) ? w2 : w3;
    int n0 = blockIdx.x * 32, k0 = blockIdx.y * 32;
    int tx = threadIdx.x, ty = threadIdx.y;
    #pragma unroll
    for (int j = 0; j < 32; j += 8)
        tile[ty + j][tx] = w[(size_t)(k0 + ty + j) * D_MODEL + n0 + tx];
    __syncthreads();
    #pragma unroll
    for (int j = 0; j < 32; j += 8) {
        float v = tile[tx][ty + j];
        __nv_bfloat16 h, l;
        bf16_split(v, h, l);
        size_t o = (size_t)wsel * WSZ + (size_t)(n0 + ty + j) * D_MODEL + k0 + tx;
        wh[o] = h; wl[o] = l;
    }
}

// ============================================================
// Kernel 1: LN(eps 1e-5) + sinusoidal PE -> fp32 + bf16 split
// ============================================================
__global__ __launch_bounds__(128) void ln1_pe_kernel(
    const float* __restrict__ x,
    const float* __restrict__ gam,
    const float* __restrict__ bet,
    float* __restrict__ h_out,
    __nv_bfloat16* __restrict__ hh_out,
    __nv_bfloat16* __restrict__ hl_out)
{
    int r   = blockIdx.x;
    int tid = threadIdx.x;
    const float4 xv = ((const float4*)(x + (size_t)r * D_MODEL))[tid];

    float sum = xv.x + xv.y + xv.z + xv.w;
    float sq  = xv.x*xv.x + xv.y*xv.y + xv.z*xv.z + xv.w*xv.w;
    #pragma unroll
    for (int off = 16; off; off >>= 1) {
        sum += __shfl_xor_sync(0xffffffffu, sum, off);
        sq  += __shfl_xor_sync(0xffffffffu, sq,  off);
    }
    __shared__ float s1[4], s2[4];
    if ((tid & 31) == 0) { s1[tid >> 5] = sum; s2[tid >> 5] = sq; }
    __syncthreads();
    sum = s1[0] + s1[1] + s1[2] + s1[3];
    sq  = s2[0] + s2[1] + s2[2] + s2[3];

    float mean = sum * (1.0f / D_MODEL);
    float var  = sq  * (1.0f / D_MODEL) - mean * mean;
    float rstd = rsqrtf(var + 1e-5f);

    int t  = r & (T_LEN - 1);
    int c0 = tid * 4;
    const float* xp = (const float*)&xv;
    float4 hv; float* hp = (float*)&hv;
    __nv_bfloat16 hb[4], lb[4];
    #pragma unroll
    for (int u = 0; u < 4; u++) {
        int c = c0 + u;
        float div = expf((float)(c & ~1) * (-9.2103403719761836f / 512.0f));
        float ang = (float)t * div;
        float pe  = (c & 1) ? cosf(ang) : sinf(ang);
        hp[u] = (xp[u] - mean) * rstd * gam[c] + bet[c] + pe;
        bf16_split(hp[u], hb[u], lb[u]);
    }
    ((float4*)(h_out + (size_t)r * D_MODEL))[tid] = hv;
    size_t base = (size_t)r * D_MODEL + c0;
    *(__nv_bfloat162*)(hh_out + base    ) = __nv_bfloat162(hb[0], hb[1]);
    *(__nv_bfloat162*)(hh_out + base + 2) = __nv_bfloat162(hb[2], hb[3]);
    *(__nv_bfloat162*)(hl_out + base    ) = __nv_bfloat162(lb[0], lb[1]);
    *(__nv_bfloat162*)(hl_out + base + 2) = __nv_bfloat162(lb[2], lb[3]);
}

// ============================================================
// Kernel 2: bf16 MMA GEMM, 3-stage cp.async pipeline + ldmatrix.
// (unchanged from R15)
// ============================================================
#define BM 128
#define BN 64
#define BK 32
#define AST 40
#define A_STAGE (BM * AST)
#define W_STAGE (BN * AST)
#define STAGES 3
#define GEMM_SMEM (STAGES * (A_STAGE + W_STAGE) * 2 * 2)   // 92160 bytes

template<int MODE>
__global__ __launch_bounds__(256, 2) void gemm_bf16(
    const __nv_bfloat16* __restrict__ Ah, const __nv_bfloat16* __restrict__ Al,
    const __nv_bfloat16* __restrict__ Wh_base, const __nv_bfloat16* __restrict__ Wl_base,
    float* __restrict__ C,
    __nv_bfloat16* __restrict__ Qh, __nv_bfloat16* __restrict__ Ql,
    __nv_bfloat16* __restrict__ Kh, __nv_bfloat16* __restrict__ Kl,
    __nv_bfloat16* __restrict__ Vh, __nv_bfloat16* __restrict__ Vl)
{
    const int K = 512, N = 512;
    const int WSZ = D_MODEL * D_MODEL;
    int z = (MODE == 1) ? blockIdx.z : 0;
    const __nv_bfloat16* Wh = Wh_base + (size_t)z * WSZ;
    const __nv_bfloat16* Wl = Wl_base + (size_t)z * WSZ;

    extern __shared__ __nv_bfloat16 smem[];
    __nv_bfloat16* pAh = smem;
    __nv_bfloat16* pAl = pAh + STAGES * A_STAGE;
    __nv_bfloat16* pWh = pAl + STAGES * A_STAGE;
    __nv_bfloat16* pWl = pWh + STAGES * W_STAGE;

    uint bAh = (uint)__cvta_generic_to_shared(pAh);
    uint bAl = (uint)__cvta_generic_to_shared(pAl);
    uint bWh = (uint)__cvta_generic_to_shared(pWh);
    uint bWl = (uint)__cvta_generic_to_shared(pWl);

    int tid  = threadIdx.x;
    int m0   = blockIdx.y * BM;
    int n0   = blockIdx.x * BN;
    int warp = tid >> 5, lane = tid & 31;
    int wm   = (warp >> 1) * 32;
    int wn   = (warp & 1) * 32;
    int g    = lane >> 2, t = lane & 3;

    int ar = tid >> 2;
    int ac = (tid & 3) << 3;
    const size_t gAoff0 = (size_t)(m0 + ar) * K + ac;
    const size_t gAoff1 = (size_t)(m0 + ar + 64) * K + ac;
    const size_t gWoff  = (size_t)(n0 + ar) * K + ac;
    const uint sAoff0 = (ar * AST + ac) * 2;
    const uint sAoff1 = ((ar + 64) * AST + ac) * 2;
    const uint sWoff  = (ar * AST + ac) * 2;

    const int aRow = (wm + (lane & 15)) * AST + ((lane >> 4) << 3);
    const int bRow = (wn + (lane & 7) + ((lane >> 4) << 3)) * AST + (((lane >> 3) & 1) << 3);

    float acc[2][4][4];
    #pragma unroll
    for (int i = 0; i < 2; i++)
        #pragma unroll
        for (int j = 0; j < 4; j++)
            #pragma unroll
            for (int e = 0; e < 4; e++) acc[i][j][e] = 0.0f;

    auto issue = [&](int k0, int st) {
        uint sa = st * A_STAGE * 2, sw = st * W_STAGE * 2;
        cp_async16(bAh + sa + sAoff0, Ah + gAoff0 + k0);
        cp_async16(bAh + sa + sAoff1, Ah + gAoff1 + k0);
        cp_async16(bAl + sa + sAoff0, Al + gAoff0 + k0);
        cp_async16(bAl + sa + sAoff1, Al + gAoff1 + k0);
        cp_async16(bWh + sw + sWoff, Wh + gWoff + k0);
        cp_async16(bWl + sw + sWoff, Wl + gWoff + k0);
    };

    issue(0, 0); cp_commit();
    issue(BK, 1); cp_commit();
    const int NT = K / BK;  // 16
    for (int it = 0; it < NT; it++) {
        int st = it % STAGES;
        if (it + 2 < NT) {
            cp_wait<1>(); __syncthreads();
            issue((it + 2) * BK, (it + 2) % STAGES); cp_commit();
        } else {
            cp_wait<0>(); __syncthreads();
        }

        uint sa = st * A_STAGE * 2, sw = st * W_STAGE * 2;
        #pragma unroll
        for (int ks = 0; ks < BK; ks += 16) {
            uint a_h[2][4], a_l[2][4], b_h[2][4], b_l[2][4];
            #pragma unroll
            for (int mt = 0; mt < 2; mt++) {
                uint off = sa + (aRow + mt * 16 * AST + ks) * 2;
                ldsm4(a_h[mt], bAh + off);
                ldsm4(a_l[mt], bAl + off);
            }
            #pragma unroll
            for (int nt2 = 0; nt2 < 2; nt2++) {
                uint off = sw + (bRow + nt2 * 16 * AST + ks) * 2;
                ldsm4(b_h[nt2], bWh + off);
                ldsm4(b_l[nt2], bWl + off);
            }
            #pragma unroll
            for (int mt = 0; mt < 2; mt++)
                #pragma unroll
                for (int nt = 0; nt < 4; nt++) {
                    const uint* bh = &b_h[nt >> 1][(nt & 1) * 2];
                    const uint* bl = &b_l[nt >> 1][(nt & 1) * 2];
                    mma_bf16(acc[mt][nt], a_h[mt], bh);
                    mma_bf16(acc[mt][nt], a_h[mt], bl);
                    mma_bf16(acc[mt][nt], a_l[mt], bh);
                }
        }
        __syncthreads();
    }

    float ascale = (MODE == 1 && z == 0) ? 0.125f : 1.0f;
    __nv_bfloat16* Ch = (z == 0) ? Qh : (z == 1) ? Kh : Vh;
    __nv_bfloat16* Cl = (z == 0) ? Ql : (z == 1) ? Kl : Vl;

    #pragma unroll
    for (int mt = 0; mt < 2; mt++)
        #pragma unroll
        for (int nt = 0; nt < 4; nt++) {
            float* a = acc[mt][nt];
            int m = m0 + wm + mt * 16 + g;
            int n = n0 + wn + nt * 8 + t * 2;
            if (MODE == 0) {
                *(float2*)(C + (size_t)m * N + n)       = make_float2(a[0], a[1]);
                *(float2*)(C + (size_t)(m + 8) * N + n) = make_float2(a[2], a[3]);
            } else {
                #pragma unroll
                for (int half = 0; half < 2; half++) {
                    int mm = m + half * 8;
                    int bb = mm >> 11, tt = mm & (T_LEN - 1);
                    int hh = n >> 6,  dd = n & 63;
                    size_t addr = (((size_t)bb * N_HEADS + hh) * T_LEN + tt) * D_K + dd;
                    __nv_bfloat16 h0, l0, h1, l1;
                    bf16_split(a[half*2+0] * ascale, h0, l0);
                    bf16_split(a[half*2+1] * ascale, h1, l1);
                    *(__nv_bfloat162*)(Ch + addr) = __nv_bfloat162(h0, h1);
                    *(__nv_bfloat162*)(Cl + addr) = __nv_bfloat162(l0, l1);
                }
            }
        }
}

// ============================================================
// Kernel 3: bf16 MMA causal flash attention.
// 256 threads = 8 warps, q-block 128 rows, KV tiles 64 via
// 2-stage cp.async double buffer, ONE barrier per tile.
// Fully-masked tiles skipped per-warp. grid (16 reversed, 32).
// ============================================================
#define ATT_ARR   (64 * 72)                 // elems per array
#define ATT_STAGE (4 * ATT_ARR)             // 4 arrays (Kh,Kl,Vh,Vl)
#define ATT_SMEM  (2 * ATT_STAGE * 2)       // bytes = 73728

__global__ __launch_bounds__(256) void attn_mma(
    const __nv_bfloat16* __restrict__ qh_in, const __nv_bfloat16* __restrict__ ql_in,
    const __nv_bfloat16* __restrict__ kh_in, const __nv_bfloat16* __restrict__ kl_in,
    const __nv_bfloat16* __restrict__ vh_in, const __nv_bfloat16* __restrict__ vl_in,
    __nv_bfloat16* __restrict__ oh_out, __nv_bfloat16* __restrict__ ol_out)
{
    int qb   = (int)gridDim.x - 1 - (int)blockIdx.x;   // 0..15, big first
    int bh   = blockIdx.y;
    int b    = bh >> 3, h = bh & 7;
    int tid  = threadIdx.x;
    int warp = tid >> 5, lane = tid & 31;
    int g    = lane >> 2, t = lane & 3;
    int q0   = qb * 128 + warp * 16;

    extern __shared__ __nv_bfloat16 asmem[];   // [2][4][64][72]
    uint sb = (uint)__cvta_generic_to_shared(asmem);
    const uint aKh = 0, aKl = ATT_ARR * 2, aVh = 2 * ATT_ARR * 2, aVl = 3 * ATT_ARR * 2;
    const uint stg = ATT_STAGE * 2;
    // ldmatrix lane offset within an array: row (lane&15), col-half (lane>>4)*8
    const uint lmo = ((lane & 15) * 72 + ((lane >> 4) << 3)) * 2;

    // cp.async indices: 256 threads cover 64 rows x 64 elems per array
    int tr = tid >> 2;
    int tc = (tid & 3) << 4;                  // {0,16,32,48}
    const uint sdst = (tr * 72 + tc) * 2;
    const size_t gKV = (size_t)bh * T_LEN * D_K + (size_t)tr * D_K + tc;

    auto issue = [&](int kt, int st) {
        size_t goff = gKV + (size_t)kt * 64 * D_K;
        uint d = sb + st * stg + sdst;
        cp_async16(d + aKh,      kh_in + goff);
        cp_async16(d + aKh + 16, kh_in + goff + 8);
        cp_async16(d + aKl,      kl_in + goff);
        cp_async16(d + aKl + 16, kl_in + goff + 8);
        cp_async16(d + aVh,      vh_in + goff);
        cp_async16(d + aVh + 16, vh_in + goff + 8);
        cp_async16(d + aVl,      vl_in + goff);
        cp_async16(d + aVl + 16, vl_in + goff + 8);
    };

    // ---- Q fragments (registers, whole kernel) ----
    uint qfh[4][4], qfl[4][4];
    {
        const size_t qb0 = (size_t)bh * T_LEN * D_K;
        #pragma unroll
        for (int c = 0; c < 4; c++)
            #pragma unroll
            for (int p = 0; p < 4; p++) {
                int row = q0 + g + (p & 1) * 8;
                int col = c * 16 + t * 2 + (p >> 1) * 8;
                qfh[c][p] = *(const uint*)(qh_in + qb0 + (size_t)row * D_K + col);
                qfl[c][p] = *(const uint*)(ql_in + qb0 + (size_t)row * D_K + col);
            }
    }

    float o_[8][4];
    #pragma unroll
    for (int j = 0; j < 8; j++)
        #pragma unroll
        for (int e = 0; e < 4; e++) o_[j][e] = 0.0f;
    float mrow0 = -1e30f, mrow1 = -1e30f, lsum0 = 0.0f, lsum1 = 0.0f;

    int ntiles = 2 * qb + 2;
    issue(0, 0); cp_commit();

    for (int kt = 0; kt < ntiles; kt++) {
        int st = kt & 1;
        int kv0 = kt * 64;
        cp_wait<0>();
        __syncthreads();
        if (kt + 1 < ntiles) { issue(kt + 1, st ^ 1); cp_commit(); }

        if (kv0 > q0 + 15) continue;          // fully masked for this warp
        bool diag = (kv0 + 63 > q0);

        uint sk = sb + st * stg;

        // ---- S = Q K^T ----
        float s[8][4];
        #pragma unroll
        for (int j = 0; j < 8; j++)
            #pragma unroll
            for (int e = 0; e < 4; e++) s[j][e] = 0.0f;

        #pragma unroll
        for (int c = 0; c < 4; c++)
            #pragma unroll
            for (int sv = 0; sv < 4; sv++) {
                uint kh4[4], kl4[4];
                uint off = sk + (uint)(sv * 16 * 72 + c * 16) * 2 + lmo;
                ldsm4(kh4, off + aKh);
                ldsm4(kl4, off + aKl);
                uint b0h[2] = {kh4[0], kh4[2]}, b1h[2] = {kh4[1], kh4[3]};
                uint b0l[2] = {kl4[0], kl4[2]}, b1l[2] = {kl4[1], kl4[3]};
                mma_bf16(s[sv*2],   qfh[c], b0h);
                mma_bf16(s[sv*2],   qfh[c], b0l);
                mma_bf16(s[sv*2],   qfl[c], b0h);
                mma_bf16(s[sv*2+1], qfh[c], b1h);
                mma_bf16(s[sv*2+1], qfh[c], b1l);
                mma_bf16(s[sv*2+1], qfl[c], b1h);
            }

        // ---- causal mask (diagonal tiles only) ----
        if (diag) {
            #pragma unroll
            for (int j = 0; j < 8; j++)
                #pragma unroll
                for (int e = 0; e < 4; e++) {
                    int gcol = kv0 + 8*j + t*2 + (e & 1);
                    int grow = q0 + g + (e >> 1) * 8;
                    if (gcol > grow) s[j][e] = -1e30f;
                }
        }

        // ---- online softmax ----
        float mx0 = -1e30f, mx1 = -1e30f;
        #pragma unroll
        for (int j = 0; j < 8; j++) {
            mx0 = fmaxf(mx0, fmaxf(s[j][0], s[j][1]));
            mx1 = fmaxf(mx1, fmaxf(s[j][2], s[j][3]));
        }
        mx0 = fmaxf(mx0, __shfl_xor_sync(0xffffffffu, mx0, 1));
        mx0 = fmaxf(mx0, __shfl_xor_sync(0xffffffffu, mx0, 2));
        mx1 = fmaxf(mx1, __shfl_xor_sync(0xffffffffu, mx1, 1));
        mx1 = fmaxf(mx1, __shfl_xor_sync(0xffffffffu, mx1, 2));

        float nm0 = fmaxf(mrow0, mx0), nm1 = fmaxf(mrow1, mx1);
        float sc0 = __expf(mrow0 - nm0), sc1 = __expf(mrow1 - nm1);
        mrow0 = nm0; mrow1 = nm1;
        lsum0 *= sc0; lsum1 *= sc1;
        #pragma unroll
        for (int j = 0; j < 8; j++) {
            o_[j][0] *= sc0; o_[j][1] *= sc0;
            o_[j][2] *= sc1; o_[j][3] *= sc1;
        }

        float p[8][4];
        #pragma unroll
        for (int j = 0; j < 8; j++) {
            p[j][0] = __expf(s[j][0] - nm0);
            p[j][1] = __expf(s[j][1] - nm0);
            p[j][2] = __expf(s[j][2] - nm1);
            p[j][3] = __expf(s[j][3] - nm1);
            lsum0 += p[j][0] + p[j][1];
            lsum1 += p[j][2] + p[j][3];
        }

        // ---- pack P into A-fragments ----
        uint pfh[4][4], pfl[4][4];
        #pragma unroll
        for (int c2 = 0; c2 < 4; c2++) {
            int j0 = 2*c2, j1 = 2*c2 + 1;
            pfh[c2][0] = packbf(p[j0][0], p[j0][1]);
            pfh[c2][1] = packbf(p[j0][2], p[j0][3]);
            pfh[c2][2] = packbf(p[j1][0], p[j1][1]);
            pfh[c2][3] = packbf(p[j1][2], p[j1][3]);
            pfl[c2][0] = packbf(p[j0][0] - lo16f(pfh[c2][0]), p[j0][1] - hi16f(pfh[c2][0]));
            pfl[c2][1] = packbf(p[j0][2] - lo16f(pfh[c2][1]), p[j0][3] - hi16f(pfh[c2][1]));
            pfl[c2][2] = packbf(p[j1][0] - lo16f(pfh[c2][2]), p[j1][1] - hi16f(pfh[c2][2]));
            pfl[c2][3] = packbf(p[j1][2] - lo16f(pfh[c2][3]), p[j1][3] - hi16f(pfh[c2][3]));
        }

        // ---- O += P V  (V^T fragments via ldmatrix.trans) ----
        #pragma unroll
        for (int c2 = 0; c2 < 4; c2++)
            #pragma unroll
            for (int dsub = 0; dsub < 4; dsub++) {
                uint vh4[4], vl4[4];
                uint off = sk + (uint)(c2 * 16 * 72 + dsub * 16) * 2 + lmo;
                ldsm4t(vh4, off + aVh);
                ldsm4t(vl4, off + aVl);
                mma_bf16(o_[dsub*2],   pfh[c2], &vh4[0]);
                mma_bf16(o_[dsub*2],   pfh[c2], &vl4[0]);
                mma_bf16(o_[dsub*2],   pfl[c2], &vh4[0]);
                mma_bf16(o_[dsub*2+1], pfh[c2], &vh4[2]);
                mma_bf16(o_[dsub*2+1], pfh[c2], &vl4[2]);
                mma_bf16(o_[dsub*2+1], pfl[c2], &vh4[2]);
            }
    }

    // ---- finalize ----
    lsum0 += __shfl_xor_sync(0xffffffffu, lsum0, 1);
    lsum0 += __shfl_xor_sync(0xffffffffu, lsum0, 2);
    lsum1 += __shfl_xor_sync(0xffffffffu, lsum1, 1);
    lsum1 += __shfl_xor_sync(0xffffffffu, lsum1, 2);
    float inv0 = 1.0f / lsum0, inv1 = 1.0f / lsum1;

    int row0 = q0 + g, row1 = q0 + g + 8;
    size_t ob0 = ((size_t)b * T_LEN + row0) * D_MODEL + h * D_K;
    size_t ob1 = ((size_t)b * T_LEN + row1) * D_MODEL + h * D_K;
    #pragma unroll
    for (int j = 0; j < 8; j++) {
        int col = 8*j + t*2;
        float v00 = o_[j][0] * inv0, v01 = o_[j][1] * inv0;
        float v10 = o_[j][2] * inv1, v11 = o_[j][3] * inv1;
        __nv_bfloat16 h00, l00, h01, l01, h10, l10, h11, l11;
        bf16_split(v00, h00, l00); bf16_split(v01, h01, l01);
        bf16_split(v10, h10, l10); bf16_split(v11, h11, l11);
        *(__nv_bfloat162*)(oh_out + ob0 + col) = __nv_bfloat162(h00, h01);
        *(__nv_bfloat162*)(ol_out + ob0 + col) = __nv_bfloat162(l00, l01);
        *(__nv_bfloat162*)(oh_out + ob1 + col) = __nv_bfloat162(h10, h11);
        *(__nv_bfloat162*)(ol_out + ob1 + col) = __nv_bfloat162(l10, l11);
    }
}

// ============================================================
// Kernel 4: residual + LN(eps 1e-6) + outer residual
// ============================================================
__global__ __launch_bounds__(128) void ln2_kernel(
    const float* __restrict__ y,
    const float* __restrict__ h,
    const float* __restrict__ x,
    const float* __restrict__ g2,
    const float* __restrict__ b2,
    float* __restrict__ out)
{
    int r   = blockIdx.x;
    int tid = threadIdx.x;
    float4 yv = ((const float4*)(y + (size_t)r * D_MODEL))[tid];
    float4 hv = ((const float4*)(h + (size_t)r * D_MODEL))[tid];
    float4 tv;
    tv.x = yv.x + hv.x; tv.y = yv.y + hv.y;
    tv.z = yv.z + hv.z; tv.w = yv.w + hv.w;

    float sum = tv.x + tv.y + tv.z + tv.w;
    float sq  = tv.x*tv.x + tv.y*tv.y + tv.z*tv.z + tv.w*tv.w;
    #pragma unroll
    for (int off = 16; off; off >>= 1) {
        sum += __shfl_xor_sync(0xffffffffu, sum, off);
        sq  += __shfl_xor_sync(0xffffffffu, sq,  off);
    }
    __shared__ float s1[4], s2[4];
    if ((tid & 31) == 0) { s1[tid >> 5] = sum; s2[tid >> 5] = sq; }
    __syncthreads();
    sum = s1[0] + s1[1] + s1[2] + s1[3];
    sq  = s2[0] + s2[1] + s2[2] + s2[3];

    float mean = sum * (1.0f / D_MODEL);
    float var  = sq  * (1.0f / D_MODEL) - mean * mean;
    float rstd = rsqrtf(var + 1e-6f);

    float4 xv = ((const float4*)(x + (size_t)r * D_MODEL))[tid];
    const float* tp = (const float*)&tv;
    const float* xp = (const float*)&xv;
    int c0 = tid * 4;
    float4 ov; float* op = (float*)&ov;
    #pragma unroll
    for (int u = 0; u < 4; u++) {
        int c = c0 + u;
        op[u] = (tp[u] - mean) * rstd * g2[c] + b2[c] + xp[u];
    }
    ((float4*)(out + (size_t)r * D_MODEL))[tid] = ov;
}

// ============================================================
// launch
// ============================================================
extern "C" void kernel_launch(void* const* d_in, const int* in_sizes, int n_in,
                              void* d_out, int out_size)
{
    const float* x   = (const float*)d_in[0];
    const float* g1  = (const float*)d_in[1];
    const float* b1  = (const float*)d_in[2];
    const float* wq  = (const float*)d_in[3];
    const float* wk  = (const float*)d_in[4];
    const float* wv  = (const float*)d_in[5];
    const float* wfc = (const float*)d_in[6];
    const float* g2  = (const float*)d_in[7];
    const float* b2  = (const float*)d_in[8];
    float* out = (float*)d_out;

    float *ph, *py;
    __nv_bfloat16 *phh, *phl, *pqh, *pql, *pkh, *pkl, *pvh, *pvl, *poh, *pol, *pwh, *pwl;
    cudaGetSymbolAddress((void**)&ph,  g_h);
    cudaGetSymbolAddress((void**)&phh, g_hh);
    cudaGetSymbolAddress((void**)&phl, g_hl);
    cudaGetSymbolAddress((void**)&pqh, g_qh);
    cudaGetSymbolAddress((void**)&pql, g_ql);
    cudaGetSymbolAddress((void**)&pkh, g_kh);
    cudaGetSymbolAddress((void**)&pkl, g_kl);
    cudaGetSymbolAddress((void**)&pvh, g_vh);
    cudaGetSymbolAddress((void**)&pvl, g_vl);
    cudaGetSymbolAddress((void**)&poh, g_oh);
    cudaGetSymbolAddress((void**)&pol, g_ol);
    cudaGetSymbolAddress((void**)&py,  g_y);
    cudaGetSymbolAddress((void**)&pwh, g_wh);
    cudaGetSymbolAddress((void**)&pwl, g_wl);

    static bool attr_done = false;
    if (!attr_done) {
        cudaFuncSetAttribute(gemm_bf16<0>, cudaFuncAttributeMaxDynamicSharedMemorySize, GEMM_SMEM);
        cudaFuncSetAttribute(gemm_bf16<1>, cudaFuncAttributeMaxDynamicSharedMemorySize, GEMM_SMEM);
        cudaFuncSetAttribute(attn_mma,     cudaFuncAttributeMaxDynamicSharedMemorySize, ATT_SMEM);
        attr_done = true;
    }

    const int WSZ = D_MODEL * D_MODEL;
    split_w_kernel<<<dim3(16, 16, 4), dim3(32, 8)>>>(wq, wk, wv, wfc, pwh, pwl);

    ln1_pe_kernel<<<NROWS, 128>>>(x, g1, b1, ph, phh, phl);

    gemm_bf16<1><<<dim3(D_MODEL / BN, NROWS / BM, 3), 256, GEMM_SMEM>>>(
        phh, phl, pwh, pwl, nullptr, pqh, pql, pkh, pkl, pvh, pvl);

    attn_mma<<<dim3(T_LEN / 128, BATCH * N_HEADS), 256, ATT_SMEM>>>(
        pqh, pql, pkh, pkl, pvh, pvl, poh, pol);

    gemm_bf16<0><<<dim3(D_MODEL / BN, NROWS / BM, 1), 256, GEMM_SMEM>>>(
        poh, pol, pwh + 3 * WSZ, pwl + 3 * WSZ, py,
        nullptr, nullptr, nullptr, nullptr, nullptr, nullptr);

    ln2_kernel<<<NROWS, 128>>>(py, ph, x, g2, b2, out);
}